// round 13
// baseline (speedup 1.0000x reference)
#include <cuda_runtime.h>
#include <cuda_bf16.h>
#include <cstdint>
#include <math.h>

// ---------------------------------------------------------------------------
// DenoiseGAT on GB300 — Round 13: 512-thread GEMM (4x4 warp grid) for better
// latency hiding; all weight prep + out-init in one kernel; temb+assemble fused.
// ---------------------------------------------------------------------------

#define NPOLY  2048
#define VPOLY  64
#define NNODES (NPOLY * VPOLY)   // 131072

__device__ __align__(128) __nv_bfloat16 g_hhi[NNODES * 256];
__device__ __align__(128) __nv_bfloat16 g_hlo[NNODES * 256];
__device__ __align__(128) float          g_proj[NNODES * 512];
__device__ __align__(128) __nv_bfloat16 g_w0hi[512 * 160], g_w0lo[512 * 160];
__device__ __align__(128) __nv_bfloat16 g_w1hi[512 * 256], g_w1lo[512 * 256];
__device__ __align__(128) __nv_bfloat16 g_w2hi[512 * 256], g_w2lo[512 * 256];
__device__ __align__(128) __nv_bfloat16 g_w3hi[256 * 256], g_w3lo[256 * 256];
__device__ __align__(128) __nv_bfloat16 g_h1hi[256 * 256], g_h1lo[256 * 256];

__device__ __forceinline__ uint32_t smem_u32(const void* p) {
    uint32_t a;
    asm("{ .reg .u64 t; cvta.to.shared.u64 t, %1; cvt.u32.u64 %0, t; }" : "=r"(a) : "l"(p));
    return a;
}
__device__ __forceinline__ void cp16(uint32_t dst, const void* src) {
    asm volatile("cp.async.cg.shared.global [%0], [%1], 16;" :: "r"(dst), "l"(src) : "memory");
}
#define CP_COMMIT() asm volatile("cp.async.commit_group;" ::: "memory")
#define CP_WAIT0()  asm volatile("cp.async.wait_group 0;" ::: "memory")
#define CP_WAIT1()  asm volatile("cp.async.wait_group 1;" ::: "memory")

__device__ __forceinline__ void ldmx4(uint32_t& r0, uint32_t& r1, uint32_t& r2, uint32_t& r3, uint32_t addr) {
    asm volatile("ldmatrix.sync.aligned.m8n8.x4.shared.b16 {%0,%1,%2,%3}, [%4];"
                 : "=r"(r0), "=r"(r1), "=r"(r2), "=r"(r3) : "r"(addr));
}
__device__ __forceinline__ void mma_bf16(float* d, const uint32_t* a, const uint32_t* b) {
    asm volatile(
        "mma.sync.aligned.m16n8k16.row.col.f32.bf16.bf16.f32 "
        "{%0,%1,%2,%3}, {%4,%5,%6,%7}, {%8,%9}, {%0,%1,%2,%3};"
        : "+f"(d[0]), "+f"(d[1]), "+f"(d[2]), "+f"(d[3])
        : "r"(a[0]), "r"(a[1]), "r"(a[2]), "r"(a[3]), "r"(b[0]), "r"(b[1]));
}

__device__ __forceinline__ float lrelu02(float x) { return x >= 0.f ? x : 0.2f * x; }
__device__ __forceinline__ float eluf(float x)    { return x > 0.f ? x : (__expf(x) - 1.f); }
__device__ __forceinline__ float siluf(float x)   { return x / (1.f + __expf(-x)); }
__device__ __forceinline__ void split_bf16(float v, __nv_bfloat16& h, __nv_bfloat16& l) {
    h = __float2bfloat16(v);
    l = __float2bfloat16(v - __bfloat162float(h));
}
__device__ __forceinline__ uint32_t pkbf2(__nv_bfloat16 a, __nv_bfloat16 b) {
    __nv_bfloat162 t(a, b);
    return *reinterpret_cast<uint32_t*>(&t);
}
__device__ __forceinline__ float bf2lo(uint32_t p) {
    __nv_bfloat162 t = *reinterpret_cast<__nv_bfloat162*>(&p);
    return __bfloat162float(t.x);
}
__device__ __forceinline__ float bf2hi(uint32_t p) {
    __nv_bfloat162 t = *reinterpret_cast<__nv_bfloat162*>(&p);
    return __bfloat162float(t.y);
}

// ---------------------------------------------------------------------------
// HMMA GEMM v2: 512 threads, warp grid 4m x 4n (32x32 warp tiles), CTA tile
// 128x128, K-tile 32, cp.async 2-stage, 80B smem rows, 2 CTAs/SM.
// MODE 0: plain store. MODE 3: fused head (silu + h2W dot -> atomicAdd out).
// ---------------------------------------------------------------------------
#define TILE_B   10240
#define STAGE_B  (4 * TILE_B)

template <int MODE>
__global__ __launch_bounds__(512, 2) void gemm_tc(
    const __nv_bfloat16* __restrict__ Ahi, const __nv_bfloat16* __restrict__ Alo,
    const __nv_bfloat16* __restrict__ Bhi, const __nv_bfloat16* __restrict__ Blo,
    int K, float* __restrict__ C, int ldc,
    const float* __restrict__ sv1, const float* __restrict__ sv2)
{
    extern __shared__ char smem[];
    const uint32_t sb = smem_u32(smem);

    const int tid  = threadIdx.x;
    const int lane = tid & 31;
    const int wid  = tid >> 5;        // 0..15
    const int wm   = wid & 3;         // 4 m-warps, 32 rows each
    const int wn   = wid >> 2;        // 4 n-warps, 32 cols each
    const int bm   = blockIdx.y * 128;
    const int bn   = blockIdx.x * 128;
    const int KT   = K >> 5;

    const int rA = tid >> 2, ch = tid & 3;   // 128 rows x 4 chunks, one each

    float acc[2][4][4];
#pragma unroll
    for (int i = 0; i < 2; i++)
#pragma unroll
        for (int j = 0; j < 4; j++)
#pragma unroll
            for (int k = 0; k < 4; k++) acc[i][j][k] = 0.f;

#define ISSUE_STAGE(kt, s)                                                            \
    do {                                                                              \
        int kof = (kt) * 32;                                                          \
        uint32_t sba = sb + (s) * STAGE_B;                                            \
        cp16(sba + rA * 80 + ch * 16,              Ahi + (size_t)(bm + rA) * K + kof + ch * 8); \
        cp16(sba + TILE_B + rA * 80 + ch * 16,     Alo + (size_t)(bm + rA) * K + kof + ch * 8); \
        cp16(sba + 2 * TILE_B + rA * 80 + ch * 16, Bhi + (size_t)(bn + rA) * K + kof + ch * 8); \
        cp16(sba + 3 * TILE_B + rA * 80 + ch * 16, Blo + (size_t)(bn + rA) * K + kof + ch * 8); \
    } while (0)

    ISSUE_STAGE(0, 0);
    CP_COMMIT();

    const int aRow  = wm * 32 + (lane & 15);
    const int aHalf = lane >> 4;
    const int bRow  = wn * 32 + (lane & 7) + ((lane >> 4) << 3);
    const int bHalf = (lane >> 3) & 1;

    for (int kt = 0; kt < KT; kt++) {
        if (kt + 1 < KT) {
            ISSUE_STAGE(kt + 1, (kt + 1) & 1);
            CP_COMMIT();
            CP_WAIT1();
        } else {
            CP_WAIT0();
        }
        __syncthreads();

        const uint32_t sba = sb + (kt & 1) * STAGE_B;
#pragma unroll
        for (int ks = 0; ks < 2; ks++) {
            uint32_t Ah[2][4], Al[2][4], Bh[4][2], Bl[4][2];
#pragma unroll
            for (int mf = 0; mf < 2; mf++) {
                uint32_t ad = sba + (aRow + mf * 16) * 80 + (2 * ks + aHalf) * 16;
                ldmx4(Ah[mf][0], Ah[mf][1], Ah[mf][2], Ah[mf][3], ad);
                ldmx4(Al[mf][0], Al[mf][1], Al[mf][2], Al[mf][3], ad + TILE_B);
            }
#pragma unroll
            for (int nfp = 0; nfp < 2; nfp++) {
                uint32_t bd = sba + 2 * TILE_B + (bRow + nfp * 16) * 80 + (2 * ks + bHalf) * 16;
                uint32_t q0, q1, q2, q3;
                ldmx4(q0, q1, q2, q3, bd);
                Bh[nfp * 2][0] = q0; Bh[nfp * 2][1] = q1;
                Bh[nfp * 2 + 1][0] = q2; Bh[nfp * 2 + 1][1] = q3;
                ldmx4(q0, q1, q2, q3, bd + TILE_B);
                Bl[nfp * 2][0] = q0; Bl[nfp * 2][1] = q1;
                Bl[nfp * 2 + 1][0] = q2; Bl[nfp * 2 + 1][1] = q3;
            }
#pragma unroll
            for (int mf = 0; mf < 2; mf++)
#pragma unroll
                for (int nf = 0; nf < 4; nf++) {
                    mma_bf16(acc[mf][nf], Ah[mf], Bh[nf]);
                    mma_bf16(acc[mf][nf], Ah[mf], Bl[nf]);
                    mma_bf16(acc[mf][nf], Al[mf], Bh[nf]);
                }
        }
        __syncthreads();
    }

#pragma unroll
    for (int mf = 0; mf < 2; mf++) {
        int m0 = bm + wm * 32 + mf * 16 + (lane >> 2);
        float r0a = 0.f, r0b = 0.f, r1a = 0.f, r1b = 0.f;
#pragma unroll
        for (int nf = 0; nf < 4; nf++) {
            int n0 = bn + wn * 32 + nf * 8 + (lane & 3) * 2;
            float v0 = acc[mf][nf][0], v1 = acc[mf][nf][1];
            float v2 = acc[mf][nf][2], v3 = acc[mf][nf][3];
            if (MODE == 3) {
                float bb0 = sv1[n0], bb1 = sv1[n0 + 1];
                v0 = siluf(v0 + bb0); v1 = siluf(v1 + bb1);
                v2 = siluf(v2 + bb0); v3 = siluf(v3 + bb1);
                float w00 = sv2[n0 * 2],     w01 = sv2[n0 * 2 + 1];
                float w10 = sv2[n0 * 2 + 2], w11 = sv2[n0 * 2 + 3];
                r0a += v0 * w00 + v1 * w10;
                r0b += v0 * w01 + v1 * w11;
                r1a += v2 * w00 + v3 * w10;
                r1b += v2 * w01 + v3 * w11;
            } else {
                *(float2*)&C[(size_t)m0 * ldc + n0]       = make_float2(v0, v1);
                *(float2*)&C[(size_t)(m0 + 8) * ldc + n0] = make_float2(v2, v3);
            }
        }
        if (MODE == 3) {
            r0a += __shfl_xor_sync(0xffffffffu, r0a, 1);
            r0a += __shfl_xor_sync(0xffffffffu, r0a, 2);
            r0b += __shfl_xor_sync(0xffffffffu, r0b, 1);
            r0b += __shfl_xor_sync(0xffffffffu, r0b, 2);
            r1a += __shfl_xor_sync(0xffffffffu, r1a, 1);
            r1a += __shfl_xor_sync(0xffffffffu, r1a, 2);
            r1b += __shfl_xor_sync(0xffffffffu, r1b, 1);
            r1b += __shfl_xor_sync(0xffffffffu, r1b, 2);
            if ((lane & 3) == 0) {
                atomicAdd(&C[(size_t)m0 * 2],           r0a);
                atomicAdd(&C[(size_t)m0 * 2 + 1],       r0b);
                atomicAdd(&C[(size_t)(m0 + 8) * 2],     r1a);
                atomicAdd(&C[(size_t)(m0 + 8) * 2 + 1], r1b);
            }
        }
    }
}

// ---------------------------------------------------------------------------
// prep_all: all weight splits + out init in one launch.
// Segments (cumulative idx): L0 cat 81920 | L1 cat 131072 | L2 cat 131072 |
// W3 t 65536 | h1W t 65536 | init_out 131072.  Total 606208 -> 2368 blocks.
// ---------------------------------------------------------------------------
__global__ void prep_all(
    const float* __restrict__ W0, const float* __restrict__ sk0,
    const float* __restrict__ W1, const float* __restrict__ sk1,
    const float* __restrict__ W2, const float* __restrict__ sk2,
    const float* __restrict__ W3, const float* __restrict__ h1W,
    const float* __restrict__ h2b, float* __restrict__ out)
{
    int idx = blockIdx.x * 256 + threadIdx.x;
    if (idx < 81920) {                       // L0: [W0|sk0]^T, Kpad=160, K=134
        int n = idx / 160, k = idx % 160;
        float v = 0.f;
        if (k < 134) v = (n < 256) ? W0[k * 256 + n] : sk0[k * 256 + (n - 256)];
        __nv_bfloat16 h, l; split_bf16(v, h, l);
        g_w0hi[idx] = h; g_w0lo[idx] = l;
    } else if (idx < 212992) {               // L1
        int i = idx - 81920, n = i >> 8, k = i & 255;
        float v = (n < 256) ? W1[k * 256 + n] : sk1[k * 256 + (n - 256)];
        __nv_bfloat16 h, l; split_bf16(v, h, l);
        g_w1hi[i] = h; g_w1lo[i] = l;
    } else if (idx < 344064) {               // L2
        int i = idx - 212992, n = i >> 8, k = i & 255;
        float v = (n < 256) ? W2[k * 256 + n] : sk2[k * 256 + (n - 256)];
        __nv_bfloat16 h, l; split_bf16(v, h, l);
        g_w2hi[i] = h; g_w2lo[i] = l;
    } else if (idx < 409600) {               // W3^T
        int i = idx - 344064, n = i >> 8, k = i & 255;
        float v = W3[k * 256 + n];
        __nv_bfloat16 h, l; split_bf16(v, h, l);
        g_w3hi[i] = h; g_w3lo[i] = l;
    } else if (idx < 475136) {               // h1W^T
        int i = idx - 409600, n = i >> 8, k = i & 255;
        float v = h1W[k * 256 + n];
        __nv_bfloat16 h, l; split_bf16(v, h, l);
        g_h1hi[i] = h; g_h1lo[i] = l;
    } else if (idx < 606208) {               // init out = h2b
        int i = idx - 475136;
        *(float2*)&out[(size_t)i * 2] = make_float2(h2b[0], h2b[1]);
    }
}

// ---------------------------------------------------------------------------
// temb + assemble fused: one block per polygon, 256 threads.
// ---------------------------------------------------------------------------
__global__ __launch_bounds__(256) void temb_assemble(
    const int* __restrict__ t, const float* __restrict__ tW,
    const float* __restrict__ tb, const float* __restrict__ x)
{
    __shared__ float pe[128], te[128];
    const int b = blockIdx.x, tid = threadIdx.x;
    float tv = (float)t[b];
    if (tid < 64) {
        float fr = expf(-logf(10000.0f) * (float)tid * (1.0f / 63.0f));
        float a = tv * fr;
        pe[tid]      = sinf(a);
        pe[tid + 64] = cosf(a);
    }
    __syncthreads();
    if (tid < 128) {
        float acc = tb[tid];
#pragma unroll 8
        for (int k = 0; k < 128; k++) acc += pe[k] * tW[k * 128 + tid];
        te[tid] = siluf(acc);
    }
    __syncthreads();
    for (int i = tid; i < 64 * 160; i += 256) {
        int v = i / 160, c = i % 160;
        int n = b * 64 + v;
        float val = 0.f;
        if (c < 2) {
            val = x[b * 128 + v * 2 + c];
        } else if (c < 6) {
            float ph  = (float)v * (6.283185307179586f / 64.f);
            float arg = (c < 4) ? ph : 2.f * ph;
            val = ((c & 1) == 0) ? sinf(arg) : cosf(arg);
        } else if (c < 134) {
            val = te[c - 6];
        }
        __nv_bfloat16 h, l;
        split_bf16(val, h, l);
        g_hhi[(size_t)n * 160 + c] = h;
        g_hlo[(size_t)n * 160 + c] = l;
    }
}

// ---------------------------------------------------------------------------
// Fused thin attention, 4 heads (R12).
// ---------------------------------------------------------------------------
__global__ __launch_bounds__(512) void att_fuse4(
    const float* __restrict__ proj,     // N x 512
    const float* __restrict__ asrc, const float* __restrict__ atgt,
    const float* __restrict__ bias)
{
    __shared__ float sS[256], sT[256], aP[256], aN[256], aSf[256], sa[256], sg[256];
    const int tid = threadIdx.x, lane = tid & 31, wid = tid >> 5;
    const int nb  = blockIdx.x * 64;

    if (tid < 256) { sa[tid] = asrc[tid]; sg[tid] = atgt[tid]; }
    __syncthreads();

    {
        const int h = lane >> 3;
        const int cbase = lane * 8;
#pragma unroll
        for (int r = 0; r < 4; r++) {
            int j = wid * 4 + r;
            const float4* rp = (const float4*)(proj + (size_t)(nb + j) * 512 + cbase);
            float4 x0 = rp[0], x1 = rp[1];
            const float* wa = sa + cbase;
            const float* wg = sg + cbase;
            float ss = x0.x * wa[0] + x0.y * wa[1] + x0.z * wa[2] + x0.w * wa[3]
                     + x1.x * wa[4] + x1.y * wa[5] + x1.z * wa[6] + x1.w * wa[7];
            float st = x0.x * wg[0] + x0.y * wg[1] + x0.z * wg[2] + x0.w * wg[3]
                     + x1.x * wg[4] + x1.y * wg[5] + x1.z * wg[6] + x1.w * wg[7];
            ss += __shfl_xor_sync(0xffffffffu, ss, 1);
            st += __shfl_xor_sync(0xffffffffu, st, 1);
            ss += __shfl_xor_sync(0xffffffffu, ss, 2);
            st += __shfl_xor_sync(0xffffffffu, st, 2);
            ss += __shfl_xor_sync(0xffffffffu, ss, 4);
            st += __shfl_xor_sync(0xffffffffu, st, 4);
            if ((lane & 7) == 0) { sS[j * 4 + h] = ss; sT[j * 4 + h] = st; }
        }
    }
    __syncthreads();

    if (tid < 256) {
        int j = tid >> 2, hh = tid & 3;
        int jp = (j + 63) & 63, jn = (j + 1) & 63;
        float tg = sT[j * 4 + hh];
        float ep = lrelu02(sS[jp * 4 + hh] + tg);
        float en = lrelu02(sS[jn * 4 + hh] + tg);
        float es = lrelu02(sS[j * 4 + hh]  + tg);
        float m  = fmaxf(ep, fmaxf(en, es));
        ep = __expf(ep - m); en = __expf(en - m); es = __expf(es - m);
        float inv = 1.f / (ep + en + es + 1e-16f);
        aP[j * 4 + hh]  = ep * inv;
        aN[j * 4 + hh]  = en * inv;
        aSf[j * 4 + hh] = es * inv;
    }
    __syncthreads();

    {
        const int c4 = (tid & 63) << 2;
        const int j0 = (tid >> 6) << 3;
        const int h  = c4 >> 6;
        const float4 bv = *(const float4*)&bias[c4];
#pragma unroll
        for (int jj = 0; jj < 8; jj++) {
            int j = j0 + jj, jp = (j + 63) & 63, jn = (j + 1) & 63;
            float ap = aP[j * 4 + h], an = aN[j * 4 + h], af = aSf[j * 4 + h];
            float4 pp = *(const float4*)&proj[(size_t)(nb + jp) * 512 + c4];
            float4 pn = *(const float4*)&proj[(size_t)(nb + jn) * 512 + c4];
            float4 ps = *(const float4*)&proj[(size_t)(nb + j)  * 512 + c4];
            float4 sk = *(const float4*)&proj[(size_t)(nb + j)  * 512 + 256 + c4];
            float v0 = eluf(ap * pp.x + an * pn.x + af * ps.x + sk.x + bv.x);
            float v1 = eluf(ap * pp.y + an * pn.y + af * ps.y + sk.y + bv.y);
            float v2 = eluf(ap * pp.z + an * pn.z + af * ps.z + sk.z + bv.z);
            float v3 = eluf(ap * pp.w + an * pn.w + af * ps.w + sk.w + bv.w);
            __nv_bfloat16 h0, l0, h1, l1, h2, l2, h3, l3;
            split_bf16(v0, h0, l0); split_bf16(v1, h1, l1);
            split_bf16(v2, h2, l2); split_bf16(v3, h3, l3);
            size_t o = (size_t)(nb + j) * 256 + c4;
            *(uint2*)&g_hhi[o] = make_uint2(pkbf2(h0, h1), pkbf2(h2, h3));
            *(uint2*)&g_hlo[o] = make_uint2(pkbf2(l0, l1), pkbf2(l2, l3));
        }
    }
}

// ---------------------------------------------------------------------------
// Fused thin attention, 1 head (R12): residual from hi+lo, no act.
// ---------------------------------------------------------------------------
__global__ __launch_bounds__(512) void att_fuse1(
    const float* __restrict__ proj,     // N x 256
    const float* __restrict__ asrc, const float* __restrict__ atgt,
    const float* __restrict__ bias)
{
    __shared__ float sS[64], sT[64], aP[64], aN[64], aSf[64], sa[256], sg[256];
    const int tid = threadIdx.x, lane = tid & 31, wid = tid >> 5;
    const int nb  = blockIdx.x * 64;

    if (tid < 256) { sa[tid] = asrc[tid]; sg[tid] = atgt[tid]; }
    __syncthreads();

    {
        const int cbase = lane * 8;
#pragma unroll
        for (int r = 0; r < 4; r++) {
            int j = wid * 4 + r;
            const float4* rp = (const float4*)(proj + (size_t)(nb + j) * 256 + cbase);
            float4 x0 = rp[0], x1 = rp[1];
            const float* wa = sa + cbase;
            const float* wg = sg + cbase;
            float ss = x0.x * wa[0] + x0.y * wa[1] + x0.z * wa[2] + x0.w * wa[3]
                     + x1.x * wa[4] + x1.y * wa[5] + x1.z * wa[6] + x1.w * wa[7];
            float st = x0.x * wg[0] + x0.y * wg[1] + x0.z * wg[2] + x0.w * wg[3]
                     + x1.x * wg[4] + x1.y * wg[5] + x1.z * wg[6] + x1.w * wg[7];
#pragma unroll
            for (int off = 16; off; off >>= 1) {
                ss += __shfl_xor_sync(0xffffffffu, ss, off);
                st += __shfl_xor_sync(0xffffffffu, st, off);
            }
            if (lane == 0) { sS[j] = ss; sT[j] = st; }
        }
    }
    __syncthreads();

    if (tid < 64) {
        int j = tid, jp = (j + 63) & 63, jn = (j + 1) & 63;
        float tg = sT[j];
        float ep = lrelu02(sS[jp] + tg);
        float en = lrelu02(sS[jn] + tg);
        float es = lrelu02(sS[j]  + tg);
        float m  = fmaxf(ep, fmaxf(en, es));
        ep = __expf(ep - m); en = __expf(en - m); es = __expf(es - m);
        float inv = 1.f / (ep + en + es + 1e-16f);
        aP[j] = ep * inv; aN[j] = en * inv; aSf[j] = es * inv;
    }
    __syncthreads();

    {
        const int c4 = (tid & 63) << 2;
        const int j0 = (tid >> 6) << 3;
        const float4 bv = *(const float4*)&bias[c4];
#pragma unroll
        for (int jj = 0; jj < 8; jj++) {
            int j = j0 + jj, jp = (j + 63) & 63, jn = (j + 1) & 63;
            float ap = aP[j], an = aN[j], af = aSf[j];
            size_t o = (size_t)(nb + j) * 256 + c4;
            uint2 uh = *(uint2*)&g_hhi[o];
            uint2 ul = *(uint2*)&g_hlo[o];
            float hp0 = bf2lo(uh.x) + bf2lo(ul.x);
            float hp1 = bf2hi(uh.x) + bf2hi(ul.x);
            float hp2 = bf2lo(uh.y) + bf2lo(ul.y);
            float hp3 = bf2hi(uh.y) + bf2hi(ul.y);
            float4 pp = *(const float4*)&proj[(size_t)(nb + jp) * 256 + c4];
            float4 pn = *(const float4*)&proj[(size_t)(nb + jn) * 256 + c4];
            float4 ps = *(const float4*)&proj[(size_t)(nb + j)  * 256 + c4];
            float v0 = ap * pp.x + an * pn.x + af * ps.x + hp0 + bv.x;
            float v1 = ap * pp.y + an * pn.y + af * ps.y + hp1 + bv.y;
            float v2 = ap * pp.z + an * pn.z + af * ps.z + hp2 + bv.z;
            float v3 = ap * pp.w + an * pn.w + af * ps.w + hp3 + bv.w;
            __nv_bfloat16 h0, l0, h1, l1, h2, l2, h3, l3;
            split_bf16(v0, h0, l0); split_bf16(v1, h1, l1);
            split_bf16(v2, h2, l2); split_bf16(v3, h3, l3);
            *(uint2*)&g_hhi[o] = make_uint2(pkbf2(h0, h1), pkbf2(h2, h3));
            *(uint2*)&g_hlo[o] = make_uint2(pkbf2(l0, l1), pkbf2(l2, l3));
        }
    }
}

// ---------------------------------------------------------------------------
extern "C" void kernel_launch(void* const* d_in, const int* in_sizes, int n_in,
                              void* d_out, int out_size)
{
    const float* x   = (const float*)d_in[0];
    const int*   t   = (const int*)  d_in[1];
    const float* tW  = (const float*)d_in[2];
    const float* tb  = (const float*)d_in[3];
    const float* W0  = (const float*)d_in[4];
    const float* as0 = (const float*)d_in[5];
    const float* at0 = (const float*)d_in[6];
    const float* b0  = (const float*)d_in[7];
    const float* W1  = (const float*)d_in[8];
    const float* as1 = (const float*)d_in[9];
    const float* at1 = (const float*)d_in[10];
    const float* b1  = (const float*)d_in[11];
    const float* W2  = (const float*)d_in[12];
    const float* as2 = (const float*)d_in[13];
    const float* at2 = (const float*)d_in[14];
    const float* b2_ = (const float*)d_in[15];
    const float* W3  = (const float*)d_in[16];
    const float* as3 = (const float*)d_in[17];
    const float* at3 = (const float*)d_in[18];
    const float* b3  = (const float*)d_in[19];
    const float* sk0 = (const float*)d_in[20];
    const float* sk1 = (const float*)d_in[21];
    const float* sk2 = (const float*)d_in[22];
    const float* h1W = (const float*)d_in[23];
    const float* h1b = (const float*)d_in[24];
    const float* h2W = (const float*)d_in[25];
    const float* h2b = (const float*)d_in[26];
    float* out = (float*)d_out;

    __nv_bfloat16 *hhi, *hlo, *w0hi, *w0lo, *w1hi, *w1lo, *w2hi, *w2lo, *w3hi, *w3lo, *h1hi, *h1lo;
    float *proj;
    cudaGetSymbolAddress((void**)&hhi,  g_hhi);
    cudaGetSymbolAddress((void**)&hlo,  g_hlo);
    cudaGetSymbolAddress((void**)&proj, g_proj);
    cudaGetSymbolAddress((void**)&w0hi, g_w0hi);  cudaGetSymbolAddress((void**)&w0lo, g_w0lo);
    cudaGetSymbolAddress((void**)&w1hi, g_w1hi);  cudaGetSymbolAddress((void**)&w1lo, g_w1lo);
    cudaGetSymbolAddress((void**)&w2hi, g_w2hi);  cudaGetSymbolAddress((void**)&w2lo, g_w2lo);
    cudaGetSymbolAddress((void**)&w3hi, g_w3hi);  cudaGetSymbolAddress((void**)&w3lo, g_w3lo);
    cudaGetSymbolAddress((void**)&h1hi, g_h1hi);  cudaGetSymbolAddress((void**)&h1lo, g_h1lo);

    const int GEMM_SMEM = 2 * STAGE_B;   // 81920
    cudaFuncSetAttribute(gemm_tc<0>, cudaFuncAttributeMaxDynamicSharedMemorySize, GEMM_SMEM);
    cudaFuncSetAttribute(gemm_tc<3>, cudaFuncAttributeMaxDynamicSharedMemorySize, GEMM_SMEM);

    const dim3 G512(4, NNODES / 128), G256(2, NNODES / 128);

    // prep everything up front (weights + out init), then temb/assemble
    prep_all<<<2368, 256>>>(W0, sk0, W1, sk1, W2, sk2, W3, h1W, h2b, out);
    temb_assemble<<<NPOLY, 256>>>(t, tW, tb, x);

    // layer 0: K=134 padded to 160
    gemm_tc<0><<<G512, 512, GEMM_SMEM>>>(hhi, hlo, w0hi, w0lo, 160, proj, 512, nullptr, nullptr);
    att_fuse4<<<NPOLY, 512>>>(proj, as0, at0, b0);

    // layer 1
    gemm_tc<0><<<G512, 512, GEMM_SMEM>>>(hhi, hlo, w1hi, w1lo, 256, proj, 512, nullptr, nullptr);
    att_fuse4<<<NPOLY, 512>>>(proj, as1, at1, b1);

    // layer 2
    gemm_tc<0><<<G512, 512, GEMM_SMEM>>>(hhi, hlo, w2hi, w2lo, 256, proj, 512, nullptr, nullptr);
    att_fuse4<<<NPOLY, 512>>>(proj, as2, at2, b2_);

    // layer 3 (NH=1, residual from hi+lo reconstruct, no act)
    gemm_tc<0><<<G256, 512, GEMM_SMEM>>>(hhi, hlo, w3hi, w3lo, 256, proj, 256, nullptr, nullptr);
    att_fuse1<<<NPOLY, 512>>>(proj, as3, at3, b3);

    // head: fused silu(h @ h1W + h1b) @ h2W + h2b -> out (atomics)
    gemm_tc<3><<<G256, 512, GEMM_SMEM>>>(hhi, hlo, h1hi, h1lo, 256, out, 2, h1b, h2W);
}

// round 14
// speedup vs baseline: 1.0010x; 1.0010x over previous
#include <cuda_runtime.h>
#include <cuda_bf16.h>
#include <cstdint>
#include <math.h>

// ---------------------------------------------------------------------------
// DenoiseGAT on GB300 — Round 13: 512-thread GEMM (4x4 warp grid) for better
// latency hiding; all weight prep + out-init in one kernel; temb+assemble fused.
// ---------------------------------------------------------------------------

#define NPOLY  2048
#define VPOLY  64
#define NNODES (NPOLY * VPOLY)   // 131072

__device__ __align__(128) __nv_bfloat16 g_hhi[NNODES * 256];
__device__ __align__(128) __nv_bfloat16 g_hlo[NNODES * 256];
__device__ __align__(128) float          g_proj[NNODES * 512];
__device__ __align__(128) __nv_bfloat16 g_w0hi[512 * 160], g_w0lo[512 * 160];
__device__ __align__(128) __nv_bfloat16 g_w1hi[512 * 256], g_w1lo[512 * 256];
__device__ __align__(128) __nv_bfloat16 g_w2hi[512 * 256], g_w2lo[512 * 256];
__device__ __align__(128) __nv_bfloat16 g_w3hi[256 * 256], g_w3lo[256 * 256];
__device__ __align__(128) __nv_bfloat16 g_h1hi[256 * 256], g_h1lo[256 * 256];

__device__ __forceinline__ uint32_t smem_u32(const void* p) {
    uint32_t a;
    asm("{ .reg .u64 t; cvta.to.shared.u64 t, %1; cvt.u32.u64 %0, t; }" : "=r"(a) : "l"(p));
    return a;
}
__device__ __forceinline__ void cp16(uint32_t dst, const void* src) {
    asm volatile("cp.async.cg.shared.global [%0], [%1], 16;" :: "r"(dst), "l"(src) : "memory");
}
#define CP_COMMIT() asm volatile("cp.async.commit_group;" ::: "memory")
#define CP_WAIT0()  asm volatile("cp.async.wait_group 0;" ::: "memory")
#define CP_WAIT1()  asm volatile("cp.async.wait_group 1;" ::: "memory")

__device__ __forceinline__ void ldmx4(uint32_t& r0, uint32_t& r1, uint32_t& r2, uint32_t& r3, uint32_t addr) {
    asm volatile("ldmatrix.sync.aligned.m8n8.x4.shared.b16 {%0,%1,%2,%3}, [%4];"
                 : "=r"(r0), "=r"(r1), "=r"(r2), "=r"(r3) : "r"(addr));
}
__device__ __forceinline__ void mma_bf16(float* d, const uint32_t* a, const uint32_t* b) {
    asm volatile(
        "mma.sync.aligned.m16n8k16.row.col.f32.bf16.bf16.f32 "
        "{%0,%1,%2,%3}, {%4,%5,%6,%7}, {%8,%9}, {%0,%1,%2,%3};"
        : "+f"(d[0]), "+f"(d[1]), "+f"(d[2]), "+f"(d[3])
        : "r"(a[0]), "r"(a[1]), "r"(a[2]), "r"(a[3]), "r"(b[0]), "r"(b[1]));
}

__device__ __forceinline__ float lrelu02(float x) { return x >= 0.f ? x : 0.2f * x; }
__device__ __forceinline__ float eluf(float x)    { return x > 0.f ? x : (__expf(x) - 1.f); }
__device__ __forceinline__ float siluf(float x)   { return x / (1.f + __expf(-x)); }
__device__ __forceinline__ void split_bf16(float v, __nv_bfloat16& h, __nv_bfloat16& l) {
    h = __float2bfloat16(v);
    l = __float2bfloat16(v - __bfloat162float(h));
}
__device__ __forceinline__ uint32_t pkbf2(__nv_bfloat16 a, __nv_bfloat16 b) {
    __nv_bfloat162 t(a, b);
    return *reinterpret_cast<uint32_t*>(&t);
}
__device__ __forceinline__ float bf2lo(uint32_t p) {
    __nv_bfloat162 t = *reinterpret_cast<__nv_bfloat162*>(&p);
    return __bfloat162float(t.x);
}
__device__ __forceinline__ float bf2hi(uint32_t p) {
    __nv_bfloat162 t = *reinterpret_cast<__nv_bfloat162*>(&p);
    return __bfloat162float(t.y);
}

// ---------------------------------------------------------------------------
// HMMA GEMM v2: 512 threads, warp grid 4m x 4n (32x32 warp tiles), CTA tile
// 128x128, K-tile 32, cp.async 2-stage, 80B smem rows, 2 CTAs/SM.
// MODE 0: plain store. MODE 3: fused head (silu + h2W dot -> atomicAdd out).
// ---------------------------------------------------------------------------
#define TILE_B   10240
#define STAGE_B  (4 * TILE_B)

template <int MODE>
__global__ __launch_bounds__(512, 2) void gemm_tc(
    const __nv_bfloat16* __restrict__ Ahi, const __nv_bfloat16* __restrict__ Alo,
    const __nv_bfloat16* __restrict__ Bhi, const __nv_bfloat16* __restrict__ Blo,
    int K, float* __restrict__ C, int ldc,
    const float* __restrict__ sv1, const float* __restrict__ sv2)
{
    extern __shared__ char smem[];
    const uint32_t sb = smem_u32(smem);

    const int tid  = threadIdx.x;
    const int lane = tid & 31;
    const int wid  = tid >> 5;        // 0..15
    const int wm   = wid & 3;         // 4 m-warps, 32 rows each
    const int wn   = wid >> 2;        // 4 n-warps, 32 cols each
    const int bm   = blockIdx.y * 128;
    const int bn   = blockIdx.x * 128;
    const int KT   = K >> 5;

    const int rA = tid >> 2, ch = tid & 3;   // 128 rows x 4 chunks, one each

    float acc[2][4][4];
#pragma unroll
    for (int i = 0; i < 2; i++)
#pragma unroll
        for (int j = 0; j < 4; j++)
#pragma unroll
            for (int k = 0; k < 4; k++) acc[i][j][k] = 0.f;

#define ISSUE_STAGE(kt, s)                                                            \
    do {                                                                              \
        int kof = (kt) * 32;                                                          \
        uint32_t sba = sb + (s) * STAGE_B;                                            \
        cp16(sba + rA * 80 + ch * 16,              Ahi + (size_t)(bm + rA) * K + kof + ch * 8); \
        cp16(sba + TILE_B + rA * 80 + ch * 16,     Alo + (size_t)(bm + rA) * K + kof + ch * 8); \
        cp16(sba + 2 * TILE_B + rA * 80 + ch * 16, Bhi + (size_t)(bn + rA) * K + kof + ch * 8); \
        cp16(sba + 3 * TILE_B + rA * 80 + ch * 16, Blo + (size_t)(bn + rA) * K + kof + ch * 8); \
    } while (0)

    ISSUE_STAGE(0, 0);
    CP_COMMIT();

    const int aRow  = wm * 32 + (lane & 15);
    const int aHalf = lane >> 4;
    const int bRow  = wn * 32 + (lane & 7) + ((lane >> 4) << 3);
    const int bHalf = (lane >> 3) & 1;

    for (int kt = 0; kt < KT; kt++) {
        if (kt + 1 < KT) {
            ISSUE_STAGE(kt + 1, (kt + 1) & 1);
            CP_COMMIT();
            CP_WAIT1();
        } else {
            CP_WAIT0();
        }
        __syncthreads();

        const uint32_t sba = sb + (kt & 1) * STAGE_B;
#pragma unroll
        for (int ks = 0; ks < 2; ks++) {
            uint32_t Ah[2][4], Al[2][4], Bh[4][2], Bl[4][2];
#pragma unroll
            for (int mf = 0; mf < 2; mf++) {
                uint32_t ad = sba + (aRow + mf * 16) * 80 + (2 * ks + aHalf) * 16;
                ldmx4(Ah[mf][0], Ah[mf][1], Ah[mf][2], Ah[mf][3], ad);
                ldmx4(Al[mf][0], Al[mf][1], Al[mf][2], Al[mf][3], ad + TILE_B);
            }
#pragma unroll
            for (int nfp = 0; nfp < 2; nfp++) {
                uint32_t bd = sba + 2 * TILE_B + (bRow + nfp * 16) * 80 + (2 * ks + bHalf) * 16;
                uint32_t q0, q1, q2, q3;
                ldmx4(q0, q1, q2, q3, bd);
                Bh[nfp * 2][0] = q0; Bh[nfp * 2][1] = q1;
                Bh[nfp * 2 + 1][0] = q2; Bh[nfp * 2 + 1][1] = q3;
                ldmx4(q0, q1, q2, q3, bd + TILE_B);
                Bl[nfp * 2][0] = q0; Bl[nfp * 2][1] = q1;
                Bl[nfp * 2 + 1][0] = q2; Bl[nfp * 2 + 1][1] = q3;
            }
#pragma unroll
            for (int mf = 0; mf < 2; mf++)
#pragma unroll
                for (int nf = 0; nf < 4; nf++) {
                    mma_bf16(acc[mf][nf], Ah[mf], Bh[nf]);
                    mma_bf16(acc[mf][nf], Ah[mf], Bl[nf]);
                    mma_bf16(acc[mf][nf], Al[mf], Bh[nf]);
                }
        }
        __syncthreads();
    }

#pragma unroll
    for (int mf = 0; mf < 2; mf++) {
        int m0 = bm + wm * 32 + mf * 16 + (lane >> 2);
        float r0a = 0.f, r0b = 0.f, r1a = 0.f, r1b = 0.f;
#pragma unroll
        for (int nf = 0; nf < 4; nf++) {
            int n0 = bn + wn * 32 + nf * 8 + (lane & 3) * 2;
            float v0 = acc[mf][nf][0], v1 = acc[mf][nf][1];
            float v2 = acc[mf][nf][2], v3 = acc[mf][nf][3];
            if (MODE == 3) {
                float bb0 = sv1[n0], bb1 = sv1[n0 + 1];
                v0 = siluf(v0 + bb0); v1 = siluf(v1 + bb1);
                v2 = siluf(v2 + bb0); v3 = siluf(v3 + bb1);
                float w00 = sv2[n0 * 2],     w01 = sv2[n0 * 2 + 1];
                float w10 = sv2[n0 * 2 + 2], w11 = sv2[n0 * 2 + 3];
                r0a += v0 * w00 + v1 * w10;
                r0b += v0 * w01 + v1 * w11;
                r1a += v2 * w00 + v3 * w10;
                r1b += v2 * w01 + v3 * w11;
            } else {
                *(float2*)&C[(size_t)m0 * ldc + n0]       = make_float2(v0, v1);
                *(float2*)&C[(size_t)(m0 + 8) * ldc + n0] = make_float2(v2, v3);
            }
        }
        if (MODE == 3) {
            r0a += __shfl_xor_sync(0xffffffffu, r0a, 1);
            r0a += __shfl_xor_sync(0xffffffffu, r0a, 2);
            r0b += __shfl_xor_sync(0xffffffffu, r0b, 1);
            r0b += __shfl_xor_sync(0xffffffffu, r0b, 2);
            r1a += __shfl_xor_sync(0xffffffffu, r1a, 1);
            r1a += __shfl_xor_sync(0xffffffffu, r1a, 2);
            r1b += __shfl_xor_sync(0xffffffffu, r1b, 1);
            r1b += __shfl_xor_sync(0xffffffffu, r1b, 2);
            if ((lane & 3) == 0) {
                atomicAdd(&C[(size_t)m0 * 2],           r0a);
                atomicAdd(&C[(size_t)m0 * 2 + 1],       r0b);
                atomicAdd(&C[(size_t)(m0 + 8) * 2],     r1a);
                atomicAdd(&C[(size_t)(m0 + 8) * 2 + 1], r1b);
            }
        }
    }
}

// ---------------------------------------------------------------------------
// prep_all: all weight splits + out init in one launch.
// Segments (cumulative idx): L0 cat 81920 | L1 cat 131072 | L2 cat 131072 |
// W3 t 65536 | h1W t 65536 | init_out 131072.  Total 606208 -> 2368 blocks.
// ---------------------------------------------------------------------------
__global__ void prep_all(
    const float* __restrict__ W0, const float* __restrict__ sk0,
    const float* __restrict__ W1, const float* __restrict__ sk1,
    const float* __restrict__ W2, const float* __restrict__ sk2,
    const float* __restrict__ W3, const float* __restrict__ h1W,
    const float* __restrict__ h2b, float* __restrict__ out)
{
    int idx = blockIdx.x * 256 + threadIdx.x;
    if (idx < 81920) {                       // L0: [W0|sk0]^T, Kpad=160, K=134
        int n = idx / 160, k = idx % 160;
        float v = 0.f;
        if (k < 134) v = (n < 256) ? W0[k * 256 + n] : sk0[k * 256 + (n - 256)];
        __nv_bfloat16 h, l; split_bf16(v, h, l);
        g_w0hi[idx] = h; g_w0lo[idx] = l;
    } else if (idx < 212992) {               // L1
        int i = idx - 81920, n = i >> 8, k = i & 255;
        float v = (n < 256) ? W1[k * 256 + n] : sk1[k * 256 + (n - 256)];
        __nv_bfloat16 h, l; split_bf16(v, h, l);
        g_w1hi[i] = h; g_w1lo[i] = l;
    } else if (idx < 344064) {               // L2
        int i = idx - 212992, n = i >> 8, k = i & 255;
        float v = (n < 256) ? W2[k * 256 + n] : sk2[k * 256 + (n - 256)];
        __nv_bfloat16 h, l; split_bf16(v, h, l);
        g_w2hi[i] = h; g_w2lo[i] = l;
    } else if (idx < 409600) {               // W3^T
        int i = idx - 344064, n = i >> 8, k = i & 255;
        float v = W3[k * 256 + n];
        __nv_bfloat16 h, l; split_bf16(v, h, l);
        g_w3hi[i] = h; g_w3lo[i] = l;
    } else if (idx < 475136) {               // h1W^T
        int i = idx - 409600, n = i >> 8, k = i & 255;
        float v = h1W[k * 256 + n];
        __nv_bfloat16 h, l; split_bf16(v, h, l);
        g_h1hi[i] = h; g_h1lo[i] = l;
    } else if (idx < 606208) {               // init out = h2b
        int i = idx - 475136;
        *(float2*)&out[(size_t)i * 2] = make_float2(h2b[0], h2b[1]);
    }
}

// ---------------------------------------------------------------------------
// temb + assemble fused: one block per polygon, 256 threads.
// ---------------------------------------------------------------------------
__global__ __launch_bounds__(256) void temb_assemble(
    const int* __restrict__ t, const float* __restrict__ tW,
    const float* __restrict__ tb, const float* __restrict__ x)
{
    __shared__ float pe[128], te[128];
    const int b = blockIdx.x, tid = threadIdx.x;
    float tv = (float)t[b];
    if (tid < 64) {
        float fr = expf(-logf(10000.0f) * (float)tid * (1.0f / 63.0f));
        float a = tv * fr;
        pe[tid]      = sinf(a);
        pe[tid + 64] = cosf(a);
    }
    __syncthreads();
    if (tid < 128) {
        float acc = tb[tid];
#pragma unroll 8
        for (int k = 0; k < 128; k++) acc += pe[k] * tW[k * 128 + tid];
        te[tid] = siluf(acc);
    }
    __syncthreads();
    for (int i = tid; i < 64 * 160; i += 256) {
        int v = i / 160, c = i % 160;
        int n = b * 64 + v;
        float val = 0.f;
        if (c < 2) {
            val = x[b * 128 + v * 2 + c];
        } else if (c < 6) {
            float ph  = (float)v * (6.283185307179586f / 64.f);
            float arg = (c < 4) ? ph : 2.f * ph;
            val = ((c & 1) == 0) ? sinf(arg) : cosf(arg);
        } else if (c < 134) {
            val = te[c - 6];
        }
        __nv_bfloat16 h, l;
        split_bf16(val, h, l);
        g_hhi[(size_t)n * 160 + c] = h;
        g_hlo[(size_t)n * 160 + c] = l;
    }
}

// ---------------------------------------------------------------------------
// Fused thin attention, 4 heads (R12).
// ---------------------------------------------------------------------------
__global__ __launch_bounds__(512) void att_fuse4(
    const float* __restrict__ proj,     // N x 512
    const float* __restrict__ asrc, const float* __restrict__ atgt,
    const float* __restrict__ bias)
{
    __shared__ float sS[256], sT[256], aP[256], aN[256], aSf[256], sa[256], sg[256];
    const int tid = threadIdx.x, lane = tid & 31, wid = tid >> 5;
    const int nb  = blockIdx.x * 64;

    if (tid < 256) { sa[tid] = asrc[tid]; sg[tid] = atgt[tid]; }
    __syncthreads();

    {
        const int h = lane >> 3;
        const int cbase = lane * 8;
#pragma unroll
        for (int r = 0; r < 4; r++) {
            int j = wid * 4 + r;
            const float4* rp = (const float4*)(proj + (size_t)(nb + j) * 512 + cbase);
            float4 x0 = rp[0], x1 = rp[1];
            const float* wa = sa + cbase;
            const float* wg = sg + cbase;
            float ss = x0.x * wa[0] + x0.y * wa[1] + x0.z * wa[2] + x0.w * wa[3]
                     + x1.x * wa[4] + x1.y * wa[5] + x1.z * wa[6] + x1.w * wa[7];
            float st = x0.x * wg[0] + x0.y * wg[1] + x0.z * wg[2] + x0.w * wg[3]
                     + x1.x * wg[4] + x1.y * wg[5] + x1.z * wg[6] + x1.w * wg[7];
            ss += __shfl_xor_sync(0xffffffffu, ss, 1);
            st += __shfl_xor_sync(0xffffffffu, st, 1);
            ss += __shfl_xor_sync(0xffffffffu, ss, 2);
            st += __shfl_xor_sync(0xffffffffu, st, 2);
            ss += __shfl_xor_sync(0xffffffffu, ss, 4);
            st += __shfl_xor_sync(0xffffffffu, st, 4);
            if ((lane & 7) == 0) { sS[j * 4 + h] = ss; sT[j * 4 + h] = st; }
        }
    }
    __syncthreads();

    if (tid < 256) {
        int j = tid >> 2, hh = tid & 3;
        int jp = (j + 63) & 63, jn = (j + 1) & 63;
        float tg = sT[j * 4 + hh];
        float ep = lrelu02(sS[jp * 4 + hh] + tg);
        float en = lrelu02(sS[jn * 4 + hh] + tg);
        float es = lrelu02(sS[j * 4 + hh]  + tg);
        float m  = fmaxf(ep, fmaxf(en, es));
        ep = __expf(ep - m); en = __expf(en - m); es = __expf(es - m);
        float inv = 1.f / (ep + en + es + 1e-16f);
        aP[j * 4 + hh]  = ep * inv;
        aN[j * 4 + hh]  = en * inv;
        aSf[j * 4 + hh] = es * inv;
    }
    __syncthreads();

    {
        const int c4 = (tid & 63) << 2;
        const int j0 = (tid >> 6) << 3;
        const int h  = c4 >> 6;
        const float4 bv = *(const float4*)&bias[c4];
#pragma unroll
        for (int jj = 0; jj < 8; jj++) {
            int j = j0 + jj, jp = (j + 63) & 63, jn = (j + 1) & 63;
            float ap = aP[j * 4 + h], an = aN[j * 4 + h], af = aSf[j * 4 + h];
            float4 pp = *(const float4*)&proj[(size_t)(nb + jp) * 512 + c4];
            float4 pn = *(const float4*)&proj[(size_t)(nb + jn) * 512 + c4];
            float4 ps = *(const float4*)&proj[(size_t)(nb + j)  * 512 + c4];
            float4 sk = *(const float4*)&proj[(size_t)(nb + j)  * 512 + 256 + c4];
            float v0 = eluf(ap * pp.x + an * pn.x + af * ps.x + sk.x + bv.x);
            float v1 = eluf(ap * pp.y + an * pn.y + af * ps.y + sk.y + bv.y);
            float v2 = eluf(ap * pp.z + an * pn.z + af * ps.z + sk.z + bv.z);
            float v3 = eluf(ap * pp.w + an * pn.w + af * ps.w + sk.w + bv.w);
            __nv_bfloat16 h0, l0, h1, l1, h2, l2, h3, l3;
            split_bf16(v0, h0, l0); split_bf16(v1, h1, l1);
            split_bf16(v2, h2, l2); split_bf16(v3, h3, l3);
            size_t o = (size_t)(nb + j) * 256 + c4;
            *(uint2*)&g_hhi[o] = make_uint2(pkbf2(h0, h1), pkbf2(h2, h3));
            *(uint2*)&g_hlo[o] = make_uint2(pkbf2(l0, l1), pkbf2(l2, l3));
        }
    }
}

// ---------------------------------------------------------------------------
// Fused thin attention, 1 head (R12): residual from hi+lo, no act.
// ---------------------------------------------------------------------------
__global__ __launch_bounds__(512) void att_fuse1(
    const float* __restrict__ proj,     // N x 256
    const float* __restrict__ asrc, const float* __restrict__ atgt,
    const float* __restrict__ bias)
{
    __shared__ float sS[64], sT[64], aP[64], aN[64], aSf[64], sa[256], sg[256];
    const int tid = threadIdx.x, lane = tid & 31, wid = tid >> 5;
    const int nb  = blockIdx.x * 64;

    if (tid < 256) { sa[tid] = asrc[tid]; sg[tid] = atgt[tid]; }
    __syncthreads();

    {
        const int cbase = lane * 8;
#pragma unroll
        for (int r = 0; r < 4; r++) {
            int j = wid * 4 + r;
            const float4* rp = (const float4*)(proj + (size_t)(nb + j) * 256 + cbase);
            float4 x0 = rp[0], x1 = rp[1];
            const float* wa = sa + cbase;
            const float* wg = sg + cbase;
            float ss = x0.x * wa[0] + x0.y * wa[1] + x0.z * wa[2] + x0.w * wa[3]
                     + x1.x * wa[4] + x1.y * wa[5] + x1.z * wa[6] + x1.w * wa[7];
            float st = x0.x * wg[0] + x0.y * wg[1] + x0.z * wg[2] + x0.w * wg[3]
                     + x1.x * wg[4] + x1.y * wg[5] + x1.z * wg[6] + x1.w * wg[7];
#pragma unroll
            for (int off = 16; off; off >>= 1) {
                ss += __shfl_xor_sync(0xffffffffu, ss, off);
                st += __shfl_xor_sync(0xffffffffu, st, off);
            }
            if (lane == 0) { sS[j] = ss; sT[j] = st; }
        }
    }
    __syncthreads();

    if (tid < 64) {
        int j = tid, jp = (j + 63) & 63, jn = (j + 1) & 63;
        float tg = sT[j];
        float ep = lrelu02(sS[jp] + tg);
        float en = lrelu02(sS[jn] + tg);
        float es = lrelu02(sS[j]  + tg);
        float m  = fmaxf(ep, fmaxf(en, es));
        ep = __expf(ep - m); en = __expf(en - m); es = __expf(es - m);
        float inv = 1.f / (ep + en + es + 1e-16f);
        aP[j] = ep * inv; aN[j] = en * inv; aSf[j] = es * inv;
    }
    __syncthreads();

    {
        const int c4 = (tid & 63) << 2;
        const int j0 = (tid >> 6) << 3;
        const float4 bv = *(const float4*)&bias[c4];
#pragma unroll
        for (int jj = 0; jj < 8; jj++) {
            int j = j0 + jj, jp = (j + 63) & 63, jn = (j + 1) & 63;
            float ap = aP[j], an = aN[j], af = aSf[j];
            size_t o = (size_t)(nb + j) * 256 + c4;
            uint2 uh = *(uint2*)&g_hhi[o];
            uint2 ul = *(uint2*)&g_hlo[o];
            float hp0 = bf2lo(uh.x) + bf2lo(ul.x);
            float hp1 = bf2hi(uh.x) + bf2hi(ul.x);
            float hp2 = bf2lo(uh.y) + bf2lo(ul.y);
            float hp3 = bf2hi(uh.y) + bf2hi(ul.y);
            float4 pp = *(const float4*)&proj[(size_t)(nb + jp) * 256 + c4];
            float4 pn = *(const float4*)&proj[(size_t)(nb + jn) * 256 + c4];
            float4 ps = *(const float4*)&proj[(size_t)(nb + j)  * 256 + c4];
            float v0 = ap * pp.x + an * pn.x + af * ps.x + hp0 + bv.x;
            float v1 = ap * pp.y + an * pn.y + af * ps.y + hp1 + bv.y;
            float v2 = ap * pp.z + an * pn.z + af * ps.z + hp2 + bv.z;
            float v3 = ap * pp.w + an * pn.w + af * ps.w + hp3 + bv.w;
            __nv_bfloat16 h0, l0, h1, l1, h2, l2, h3, l3;
            split_bf16(v0, h0, l0); split_bf16(v1, h1, l1);
            split_bf16(v2, h2, l2); split_bf16(v3, h3, l3);
            *(uint2*)&g_hhi[o] = make_uint2(pkbf2(h0, h1), pkbf2(h2, h3));
            *(uint2*)&g_hlo[o] = make_uint2(pkbf2(l0, l1), pkbf2(l2, l3));
        }
    }
}

// ---------------------------------------------------------------------------
extern "C" void kernel_launch(void* const* d_in, const int* in_sizes, int n_in,
                              void* d_out, int out_size)
{
    const float* x   = (const float*)d_in[0];
    const int*   t   = (const int*)  d_in[1];
    const float* tW  = (const float*)d_in[2];
    const float* tb  = (const float*)d_in[3];
    const float* W0  = (const float*)d_in[4];
    const float* as0 = (const float*)d_in[5];
    const float* at0 = (const float*)d_in[6];
    const float* b0  = (const float*)d_in[7];
    const float* W1  = (const float*)d_in[8];
    const float* as1 = (const float*)d_in[9];
    const float* at1 = (const float*)d_in[10];
    const float* b1  = (const float*)d_in[11];
    const float* W2  = (const float*)d_in[12];
    const float* as2 = (const float*)d_in[13];
    const float* at2 = (const float*)d_in[14];
    const float* b2_ = (const float*)d_in[15];
    const float* W3  = (const float*)d_in[16];
    const float* as3 = (const float*)d_in[17];
    const float* at3 = (const float*)d_in[18];
    const float* b3  = (const float*)d_in[19];
    const float* sk0 = (const float*)d_in[20];
    const float* sk1 = (const float*)d_in[21];
    const float* sk2 = (const float*)d_in[22];
    const float* h1W = (const float*)d_in[23];
    const float* h1b = (const float*)d_in[24];
    const float* h2W = (const float*)d_in[25];
    const float* h2b = (const float*)d_in[26];
    float* out = (float*)d_out;

    __nv_bfloat16 *hhi, *hlo, *w0hi, *w0lo, *w1hi, *w1lo, *w2hi, *w2lo, *w3hi, *w3lo, *h1hi, *h1lo;
    float *proj;
    cudaGetSymbolAddress((void**)&hhi,  g_hhi);
    cudaGetSymbolAddress((void**)&hlo,  g_hlo);
    cudaGetSymbolAddress((void**)&proj, g_proj);
    cudaGetSymbolAddress((void**)&w0hi, g_w0hi);  cudaGetSymbolAddress((void**)&w0lo, g_w0lo);
    cudaGetSymbolAddress((void**)&w1hi, g_w1hi);  cudaGetSymbolAddress((void**)&w1lo, g_w1lo);
    cudaGetSymbolAddress((void**)&w2hi, g_w2hi);  cudaGetSymbolAddress((void**)&w2lo, g_w2lo);
    cudaGetSymbolAddress((void**)&w3hi, g_w3hi);  cudaGetSymbolAddress((void**)&w3lo, g_w3lo);
    cudaGetSymbolAddress((void**)&h1hi, g_h1hi);  cudaGetSymbolAddress((void**)&h1lo, g_h1lo);

    const int GEMM_SMEM = 2 * STAGE_B;   // 81920
    cudaFuncSetAttribute(gemm_tc<0>, cudaFuncAttributeMaxDynamicSharedMemorySize, GEMM_SMEM);
    cudaFuncSetAttribute(gemm_tc<3>, cudaFuncAttributeMaxDynamicSharedMemorySize, GEMM_SMEM);

    const dim3 G512(4, NNODES / 128), G256(2, NNODES / 128);

    // prep everything up front (weights + out init), then temb/assemble
    prep_all<<<2368, 256>>>(W0, sk0, W1, sk1, W2, sk2, W3, h1W, h2b, out);
    temb_assemble<<<NPOLY, 256>>>(t, tW, tb, x);

    // layer 0: K=134 padded to 160
    gemm_tc<0><<<G512, 512, GEMM_SMEM>>>(hhi, hlo, w0hi, w0lo, 160, proj, 512, nullptr, nullptr);
    att_fuse4<<<NPOLY, 512>>>(proj, as0, at0, b0);

    // layer 1
    gemm_tc<0><<<G512, 512, GEMM_SMEM>>>(hhi, hlo, w1hi, w1lo, 256, proj, 512, nullptr, nullptr);
    att_fuse4<<<NPOLY, 512>>>(proj, as1, at1, b1);

    // layer 2
    gemm_tc<0><<<G512, 512, GEMM_SMEM>>>(hhi, hlo, w2hi, w2lo, 256, proj, 512, nullptr, nullptr);
    att_fuse4<<<NPOLY, 512>>>(proj, as2, at2, b2_);

    // layer 3 (NH=1, residual from hi+lo reconstruct, no act)
    gemm_tc<0><<<G256, 512, GEMM_SMEM>>>(hhi, hlo, w3hi, w3lo, 256, proj, 256, nullptr, nullptr);
    att_fuse1<<<NPOLY, 512>>>(proj, as3, at3, b3);

    // head: fused silu(h @ h1W + h1b) @ h2W + h2b -> out (atomics)
    gemm_tc<3><<<G256, 512, GEMM_SMEM>>>(hhi, hlo, h1hi, h1lo, 256, out, 2, h1b, h2W);
}

// round 15
// speedup vs baseline: 1.0021x; 1.0011x over previous
#include <cuda_runtime.h>
#include <cuda_bf16.h>
#include <cstdint>
#include <math.h>

// ---------------------------------------------------------------------------
// DenoiseGAT on GB300 — Round 13: 512-thread GEMM (4x4 warp grid) for better
// latency hiding; all weight prep + out-init in one kernel; temb+assemble fused.
// ---------------------------------------------------------------------------

#define NPOLY  2048
#define VPOLY  64
#define NNODES (NPOLY * VPOLY)   // 131072

__device__ __align__(128) __nv_bfloat16 g_hhi[NNODES * 256];
__device__ __align__(128) __nv_bfloat16 g_hlo[NNODES * 256];
__device__ __align__(128) float          g_proj[NNODES * 512];
__device__ __align__(128) __nv_bfloat16 g_w0hi[512 * 160], g_w0lo[512 * 160];
__device__ __align__(128) __nv_bfloat16 g_w1hi[512 * 256], g_w1lo[512 * 256];
__device__ __align__(128) __nv_bfloat16 g_w2hi[512 * 256], g_w2lo[512 * 256];
__device__ __align__(128) __nv_bfloat16 g_w3hi[256 * 256], g_w3lo[256 * 256];
__device__ __align__(128) __nv_bfloat16 g_h1hi[256 * 256], g_h1lo[256 * 256];

__device__ __forceinline__ uint32_t smem_u32(const void* p) {
    uint32_t a;
    asm("{ .reg .u64 t; cvta.to.shared.u64 t, %1; cvt.u32.u64 %0, t; }" : "=r"(a) : "l"(p));
    return a;
}
__device__ __forceinline__ void cp16(uint32_t dst, const void* src) {
    asm volatile("cp.async.cg.shared.global [%0], [%1], 16;" :: "r"(dst), "l"(src) : "memory");
}
#define CP_COMMIT() asm volatile("cp.async.commit_group;" ::: "memory")
#define CP_WAIT0()  asm volatile("cp.async.wait_group 0;" ::: "memory")
#define CP_WAIT1()  asm volatile("cp.async.wait_group 1;" ::: "memory")

__device__ __forceinline__ void ldmx4(uint32_t& r0, uint32_t& r1, uint32_t& r2, uint32_t& r3, uint32_t addr) {
    asm volatile("ldmatrix.sync.aligned.m8n8.x4.shared.b16 {%0,%1,%2,%3}, [%4];"
                 : "=r"(r0), "=r"(r1), "=r"(r2), "=r"(r3) : "r"(addr));
}
__device__ __forceinline__ void mma_bf16(float* d, const uint32_t* a, const uint32_t* b) {
    asm volatile(
        "mma.sync.aligned.m16n8k16.row.col.f32.bf16.bf16.f32 "
        "{%0,%1,%2,%3}, {%4,%5,%6,%7}, {%8,%9}, {%0,%1,%2,%3};"
        : "+f"(d[0]), "+f"(d[1]), "+f"(d[2]), "+f"(d[3])
        : "r"(a[0]), "r"(a[1]), "r"(a[2]), "r"(a[3]), "r"(b[0]), "r"(b[1]));
}

__device__ __forceinline__ float lrelu02(float x) { return x >= 0.f ? x : 0.2f * x; }
__device__ __forceinline__ float eluf(float x)    { return x > 0.f ? x : (__expf(x) - 1.f); }
__device__ __forceinline__ float siluf(float x)   { return x / (1.f + __expf(-x)); }
__device__ __forceinline__ void split_bf16(float v, __nv_bfloat16& h, __nv_bfloat16& l) {
    h = __float2bfloat16(v);
    l = __float2bfloat16(v - __bfloat162float(h));
}
__device__ __forceinline__ uint32_t pkbf2(__nv_bfloat16 a, __nv_bfloat16 b) {
    __nv_bfloat162 t(a, b);
    return *reinterpret_cast<uint32_t*>(&t);
}
__device__ __forceinline__ float bf2lo(uint32_t p) {
    __nv_bfloat162 t = *reinterpret_cast<__nv_bfloat162*>(&p);
    return __bfloat162float(t.x);
}
__device__ __forceinline__ float bf2hi(uint32_t p) {
    __nv_bfloat162 t = *reinterpret_cast<__nv_bfloat162*>(&p);
    return __bfloat162float(t.y);
}

// ---------------------------------------------------------------------------
// HMMA GEMM v2: 512 threads, warp grid 4m x 4n (32x32 warp tiles), CTA tile
// 128x128, K-tile 32, cp.async 2-stage, 80B smem rows, 2 CTAs/SM.
// MODE 0: plain store. MODE 3: fused head (silu + h2W dot -> atomicAdd out).
// ---------------------------------------------------------------------------
#define TILE_B   10240
#define STAGE_B  (4 * TILE_B)

template <int MODE>
__global__ __launch_bounds__(512, 2) void gemm_tc(
    const __nv_bfloat16* __restrict__ Ahi, const __nv_bfloat16* __restrict__ Alo,
    const __nv_bfloat16* __restrict__ Bhi, const __nv_bfloat16* __restrict__ Blo,
    int K, float* __restrict__ C, int ldc,
    const float* __restrict__ sv1, const float* __restrict__ sv2)
{
    extern __shared__ char smem[];
    const uint32_t sb = smem_u32(smem);

    const int tid  = threadIdx.x;
    const int lane = tid & 31;
    const int wid  = tid >> 5;        // 0..15
    const int wm   = wid & 3;         // 4 m-warps, 32 rows each
    const int wn   = wid >> 2;        // 4 n-warps, 32 cols each
    const int bm   = blockIdx.y * 128;
    const int bn   = blockIdx.x * 128;
    const int KT   = K >> 5;

    const int rA = tid >> 2, ch = tid & 3;   // 128 rows x 4 chunks, one each

    float acc[2][4][4];
#pragma unroll
    for (int i = 0; i < 2; i++)
#pragma unroll
        for (int j = 0; j < 4; j++)
#pragma unroll
            for (int k = 0; k < 4; k++) acc[i][j][k] = 0.f;

#define ISSUE_STAGE(kt, s)                                                            \
    do {                                                                              \
        int kof = (kt) * 32;                                                          \
        uint32_t sba = sb + (s) * STAGE_B;                                            \
        cp16(sba + rA * 80 + ch * 16,              Ahi + (size_t)(bm + rA) * K + kof + ch * 8); \
        cp16(sba + TILE_B + rA * 80 + ch * 16,     Alo + (size_t)(bm + rA) * K + kof + ch * 8); \
        cp16(sba + 2 * TILE_B + rA * 80 + ch * 16, Bhi + (size_t)(bn + rA) * K + kof + ch * 8); \
        cp16(sba + 3 * TILE_B + rA * 80 + ch * 16, Blo + (size_t)(bn + rA) * K + kof + ch * 8); \
    } while (0)

    ISSUE_STAGE(0, 0);
    CP_COMMIT();

    const int aRow  = wm * 32 + (lane & 15);
    const int aHalf = lane >> 4;
    const int bRow  = wn * 32 + (lane & 7) + ((lane >> 4) << 3);
    const int bHalf = (lane >> 3) & 1;

    for (int kt = 0; kt < KT; kt++) {
        if (kt + 1 < KT) {
            ISSUE_STAGE(kt + 1, (kt + 1) & 1);
            CP_COMMIT();
            CP_WAIT1();
        } else {
            CP_WAIT0();
        }
        __syncthreads();

        const uint32_t sba = sb + (kt & 1) * STAGE_B;
#pragma unroll
        for (int ks = 0; ks < 2; ks++) {
            uint32_t Ah[2][4], Al[2][4], Bh[4][2], Bl[4][2];
#pragma unroll
            for (int mf = 0; mf < 2; mf++) {
                uint32_t ad = sba + (aRow + mf * 16) * 80 + (2 * ks + aHalf) * 16;
                ldmx4(Ah[mf][0], Ah[mf][1], Ah[mf][2], Ah[mf][3], ad);
                ldmx4(Al[mf][0], Al[mf][1], Al[mf][2], Al[mf][3], ad + TILE_B);
            }
#pragma unroll
            for (int nfp = 0; nfp < 2; nfp++) {
                uint32_t bd = sba + 2 * TILE_B + (bRow + nfp * 16) * 80 + (2 * ks + bHalf) * 16;
                uint32_t q0, q1, q2, q3;
                ldmx4(q0, q1, q2, q3, bd);
                Bh[nfp * 2][0] = q0; Bh[nfp * 2][1] = q1;
                Bh[nfp * 2 + 1][0] = q2; Bh[nfp * 2 + 1][1] = q3;
                ldmx4(q0, q1, q2, q3, bd + TILE_B);
                Bl[nfp * 2][0] = q0; Bl[nfp * 2][1] = q1;
                Bl[nfp * 2 + 1][0] = q2; Bl[nfp * 2 + 1][1] = q3;
            }
#pragma unroll
            for (int mf = 0; mf < 2; mf++)
#pragma unroll
                for (int nf = 0; nf < 4; nf++) {
                    mma_bf16(acc[mf][nf], Ah[mf], Bh[nf]);
                    mma_bf16(acc[mf][nf], Ah[mf], Bl[nf]);
                    mma_bf16(acc[mf][nf], Al[mf], Bh[nf]);
                }
        }
        __syncthreads();
    }

#pragma unroll
    for (int mf = 0; mf < 2; mf++) {
        int m0 = bm + wm * 32 + mf * 16 + (lane >> 2);
        float r0a = 0.f, r0b = 0.f, r1a = 0.f, r1b = 0.f;
#pragma unroll
        for (int nf = 0; nf < 4; nf++) {
            int n0 = bn + wn * 32 + nf * 8 + (lane & 3) * 2;
            float v0 = acc[mf][nf][0], v1 = acc[mf][nf][1];
            float v2 = acc[mf][nf][2], v3 = acc[mf][nf][3];
            if (MODE == 3) {
                float bb0 = sv1[n0], bb1 = sv1[n0 + 1];
                v0 = siluf(v0 + bb0); v1 = siluf(v1 + bb1);
                v2 = siluf(v2 + bb0); v3 = siluf(v3 + bb1);
                float w00 = sv2[n0 * 2],     w01 = sv2[n0 * 2 + 1];
                float w10 = sv2[n0 * 2 + 2], w11 = sv2[n0 * 2 + 3];
                r0a += v0 * w00 + v1 * w10;
                r0b += v0 * w01 + v1 * w11;
                r1a += v2 * w00 + v3 * w10;
                r1b += v2 * w01 + v3 * w11;
            } else {
                *(float2*)&C[(size_t)m0 * ldc + n0]       = make_float2(v0, v1);
                *(float2*)&C[(size_t)(m0 + 8) * ldc + n0] = make_float2(v2, v3);
            }
        }
        if (MODE == 3) {
            r0a += __shfl_xor_sync(0xffffffffu, r0a, 1);
            r0a += __shfl_xor_sync(0xffffffffu, r0a, 2);
            r0b += __shfl_xor_sync(0xffffffffu, r0b, 1);
            r0b += __shfl_xor_sync(0xffffffffu, r0b, 2);
            r1a += __shfl_xor_sync(0xffffffffu, r1a, 1);
            r1a += __shfl_xor_sync(0xffffffffu, r1a, 2);
            r1b += __shfl_xor_sync(0xffffffffu, r1b, 1);
            r1b += __shfl_xor_sync(0xffffffffu, r1b, 2);
            if ((lane & 3) == 0) {
                atomicAdd(&C[(size_t)m0 * 2],           r0a);
                atomicAdd(&C[(size_t)m0 * 2 + 1],       r0b);
                atomicAdd(&C[(size_t)(m0 + 8) * 2],     r1a);
                atomicAdd(&C[(size_t)(m0 + 8) * 2 + 1], r1b);
            }
        }
    }
}

// ---------------------------------------------------------------------------
// prep_all: all weight splits + out init in one launch.
// Segments (cumulative idx): L0 cat 81920 | L1 cat 131072 | L2 cat 131072 |
// W3 t 65536 | h1W t 65536 | init_out 131072.  Total 606208 -> 2368 blocks.
// ---------------------------------------------------------------------------
__global__ void prep_all(
    const float* __restrict__ W0, const float* __restrict__ sk0,
    const float* __restrict__ W1, const float* __restrict__ sk1,
    const float* __restrict__ W2, const float* __restrict__ sk2,
    const float* __restrict__ W3, const float* __restrict__ h1W,
    const float* __restrict__ h2b, float* __restrict__ out)
{
    int idx = blockIdx.x * 256 + threadIdx.x;
    if (idx < 81920) {                       // L0: [W0|sk0]^T, Kpad=160, K=134
        int n = idx / 160, k = idx % 160;
        float v = 0.f;
        if (k < 134) v = (n < 256) ? W0[k * 256 + n] : sk0[k * 256 + (n - 256)];
        __nv_bfloat16 h, l; split_bf16(v, h, l);
        g_w0hi[idx] = h; g_w0lo[idx] = l;
    } else if (idx < 212992) {               // L1
        int i = idx - 81920, n = i >> 8, k = i & 255;
        float v = (n < 256) ? W1[k * 256 + n] : sk1[k * 256 + (n - 256)];
        __nv_bfloat16 h, l; split_bf16(v, h, l);
        g_w1hi[i] = h; g_w1lo[i] = l;
    } else if (idx < 344064) {               // L2
        int i = idx - 212992, n = i >> 8, k = i & 255;
        float v = (n < 256) ? W2[k * 256 + n] : sk2[k * 256 + (n - 256)];
        __nv_bfloat16 h, l; split_bf16(v, h, l);
        g_w2hi[i] = h; g_w2lo[i] = l;
    } else if (idx < 409600) {               // W3^T
        int i = idx - 344064, n = i >> 8, k = i & 255;
        float v = W3[k * 256 + n];
        __nv_bfloat16 h, l; split_bf16(v, h, l);
        g_w3hi[i] = h; g_w3lo[i] = l;
    } else if (idx < 475136) {               // h1W^T
        int i = idx - 409600, n = i >> 8, k = i & 255;
        float v = h1W[k * 256 + n];
        __nv_bfloat16 h, l; split_bf16(v, h, l);
        g_h1hi[i] = h; g_h1lo[i] = l;
    } else if (idx < 606208) {               // init out = h2b
        int i = idx - 475136;
        *(float2*)&out[(size_t)i * 2] = make_float2(h2b[0], h2b[1]);
    }
}

// ---------------------------------------------------------------------------
// temb + assemble fused: one block per polygon, 256 threads.
// ---------------------------------------------------------------------------
__global__ __launch_bounds__(256) void temb_assemble(
    const int* __restrict__ t, const float* __restrict__ tW,
    const float* __restrict__ tb, const float* __restrict__ x)
{
    __shared__ float pe[128], te[128];
    const int b = blockIdx.x, tid = threadIdx.x;
    float tv = (float)t[b];
    if (tid < 64) {
        float fr = expf(-logf(10000.0f) * (float)tid * (1.0f / 63.0f));
        float a = tv * fr;
        pe[tid]      = sinf(a);
        pe[tid + 64] = cosf(a);
    }
    __syncthreads();
    if (tid < 128) {
        float acc = tb[tid];
#pragma unroll 8
        for (int k = 0; k < 128; k++) acc += pe[k] * tW[k * 128 + tid];
        te[tid] = siluf(acc);
    }
    __syncthreads();
    for (int i = tid; i < 64 * 160; i += 256) {
        int v = i / 160, c = i % 160;
        int n = b * 64 + v;
        float val = 0.f;
        if (c < 2) {
            val = x[b * 128 + v * 2 + c];
        } else if (c < 6) {
            float ph  = (float)v * (6.283185307179586f / 64.f);
            float arg = (c < 4) ? ph : 2.f * ph;
            val = ((c & 1) == 0) ? sinf(arg) : cosf(arg);
        } else if (c < 134) {
            val = te[c - 6];
        }
        __nv_bfloat16 h, l;
        split_bf16(val, h, l);
        g_hhi[(size_t)n * 160 + c] = h;
        g_hlo[(size_t)n * 160 + c] = l;
    }
}

// ---------------------------------------------------------------------------
// Fused thin attention, 4 heads (R12).
// ---------------------------------------------------------------------------
__global__ __launch_bounds__(512) void att_fuse4(
    const float* __restrict__ proj,     // N x 512
    const float* __restrict__ asrc, const float* __restrict__ atgt,
    const float* __restrict__ bias)
{
    __shared__ float sS[256], sT[256], aP[256], aN[256], aSf[256], sa[256], sg[256];
    const int tid = threadIdx.x, lane = tid & 31, wid = tid >> 5;
    const int nb  = blockIdx.x * 64;

    if (tid < 256) { sa[tid] = asrc[tid]; sg[tid] = atgt[tid]; }
    __syncthreads();

    {
        const int h = lane >> 3;
        const int cbase = lane * 8;
#pragma unroll
        for (int r = 0; r < 4; r++) {
            int j = wid * 4 + r;
            const float4* rp = (const float4*)(proj + (size_t)(nb + j) * 512 + cbase);
            float4 x0 = rp[0], x1 = rp[1];
            const float* wa = sa + cbase;
            const float* wg = sg + cbase;
            float ss = x0.x * wa[0] + x0.y * wa[1] + x0.z * wa[2] + x0.w * wa[3]
                     + x1.x * wa[4] + x1.y * wa[5] + x1.z * wa[6] + x1.w * wa[7];
            float st = x0.x * wg[0] + x0.y * wg[1] + x0.z * wg[2] + x0.w * wg[3]
                     + x1.x * wg[4] + x1.y * wg[5] + x1.z * wg[6] + x1.w * wg[7];
            ss += __shfl_xor_sync(0xffffffffu, ss, 1);
            st += __shfl_xor_sync(0xffffffffu, st, 1);
            ss += __shfl_xor_sync(0xffffffffu, ss, 2);
            st += __shfl_xor_sync(0xffffffffu, st, 2);
            ss += __shfl_xor_sync(0xffffffffu, ss, 4);
            st += __shfl_xor_sync(0xffffffffu, st, 4);
            if ((lane & 7) == 0) { sS[j * 4 + h] = ss; sT[j * 4 + h] = st; }
        }
    }
    __syncthreads();

    if (tid < 256) {
        int j = tid >> 2, hh = tid & 3;
        int jp = (j + 63) & 63, jn = (j + 1) & 63;
        float tg = sT[j * 4 + hh];
        float ep = lrelu02(sS[jp * 4 + hh] + tg);
        float en = lrelu02(sS[jn * 4 + hh] + tg);
        float es = lrelu02(sS[j * 4 + hh]  + tg);
        float m  = fmaxf(ep, fmaxf(en, es));
        ep = __expf(ep - m); en = __expf(en - m); es = __expf(es - m);
        float inv = 1.f / (ep + en + es + 1e-16f);
        aP[j * 4 + hh]  = ep * inv;
        aN[j * 4 + hh]  = en * inv;
        aSf[j * 4 + hh] = es * inv;
    }
    __syncthreads();

    {
        const int c4 = (tid & 63) << 2;
        const int j0 = (tid >> 6) << 3;
        const int h  = c4 >> 6;
        const float4 bv = *(const float4*)&bias[c4];
#pragma unroll
        for (int jj = 0; jj < 8; jj++) {
            int j = j0 + jj, jp = (j + 63) & 63, jn = (j + 1) & 63;
            float ap = aP[j * 4 + h], an = aN[j * 4 + h], af = aSf[j * 4 + h];
            float4 pp = *(const float4*)&proj[(size_t)(nb + jp) * 512 + c4];
            float4 pn = *(const float4*)&proj[(size_t)(nb + jn) * 512 + c4];
            float4 ps = *(const float4*)&proj[(size_t)(nb + j)  * 512 + c4];
            float4 sk = *(const float4*)&proj[(size_t)(nb + j)  * 512 + 256 + c4];
            float v0 = eluf(ap * pp.x + an * pn.x + af * ps.x + sk.x + bv.x);
            float v1 = eluf(ap * pp.y + an * pn.y + af * ps.y + sk.y + bv.y);
            float v2 = eluf(ap * pp.z + an * pn.z + af * ps.z + sk.z + bv.z);
            float v3 = eluf(ap * pp.w + an * pn.w + af * ps.w + sk.w + bv.w);
            __nv_bfloat16 h0, l0, h1, l1, h2, l2, h3, l3;
            split_bf16(v0, h0, l0); split_bf16(v1, h1, l1);
            split_bf16(v2, h2, l2); split_bf16(v3, h3, l3);
            size_t o = (size_t)(nb + j) * 256 + c4;
            *(uint2*)&g_hhi[o] = make_uint2(pkbf2(h0, h1), pkbf2(h2, h3));
            *(uint2*)&g_hlo[o] = make_uint2(pkbf2(l0, l1), pkbf2(l2, l3));
        }
    }
}

// ---------------------------------------------------------------------------
// Fused thin attention, 1 head (R12): residual from hi+lo, no act.
// ---------------------------------------------------------------------------
__global__ __launch_bounds__(512) void att_fuse1(
    const float* __restrict__ proj,     // N x 256
    const float* __restrict__ asrc, const float* __restrict__ atgt,
    const float* __restrict__ bias)
{
    __shared__ float sS[64], sT[64], aP[64], aN[64], aSf[64], sa[256], sg[256];
    const int tid = threadIdx.x, lane = tid & 31, wid = tid >> 5;
    const int nb  = blockIdx.x * 64;

    if (tid < 256) { sa[tid] = asrc[tid]; sg[tid] = atgt[tid]; }
    __syncthreads();

    {
        const int cbase = lane * 8;
#pragma unroll
        for (int r = 0; r < 4; r++) {
            int j = wid * 4 + r;
            const float4* rp = (const float4*)(proj + (size_t)(nb + j) * 256 + cbase);
            float4 x0 = rp[0], x1 = rp[1];
            const float* wa = sa + cbase;
            const float* wg = sg + cbase;
            float ss = x0.x * wa[0] + x0.y * wa[1] + x0.z * wa[2] + x0.w * wa[3]
                     + x1.x * wa[4] + x1.y * wa[5] + x1.z * wa[6] + x1.w * wa[7];
            float st = x0.x * wg[0] + x0.y * wg[1] + x0.z * wg[2] + x0.w * wg[3]
                     + x1.x * wg[4] + x1.y * wg[5] + x1.z * wg[6] + x1.w * wg[7];
#pragma unroll
            for (int off = 16; off; off >>= 1) {
                ss += __shfl_xor_sync(0xffffffffu, ss, off);
                st += __shfl_xor_sync(0xffffffffu, st, off);
            }
            if (lane == 0) { sS[j] = ss; sT[j] = st; }
        }
    }
    __syncthreads();

    if (tid < 64) {
        int j = tid, jp = (j + 63) & 63, jn = (j + 1) & 63;
        float tg = sT[j];
        float ep = lrelu02(sS[jp] + tg);
        float en = lrelu02(sS[jn] + tg);
        float es = lrelu02(sS[j]  + tg);
        float m  = fmaxf(ep, fmaxf(en, es));
        ep = __expf(ep - m); en = __expf(en - m); es = __expf(es - m);
        float inv = 1.f / (ep + en + es + 1e-16f);
        aP[j] = ep * inv; aN[j] = en * inv; aSf[j] = es * inv;
    }
    __syncthreads();

    {
        const int c4 = (tid & 63) << 2;
        const int j0 = (tid >> 6) << 3;
        const float4 bv = *(const float4*)&bias[c4];
#pragma unroll
        for (int jj = 0; jj < 8; jj++) {
            int j = j0 + jj, jp = (j + 63) & 63, jn = (j + 1) & 63;
            float ap = aP[j], an = aN[j], af = aSf[j];
            size_t o = (size_t)(nb + j) * 256 + c4;
            uint2 uh = *(uint2*)&g_hhi[o];
            uint2 ul = *(uint2*)&g_hlo[o];
            float hp0 = bf2lo(uh.x) + bf2lo(ul.x);
            float hp1 = bf2hi(uh.x) + bf2hi(ul.x);
            float hp2 = bf2lo(uh.y) + bf2lo(ul.y);
            float hp3 = bf2hi(uh.y) + bf2hi(ul.y);
            float4 pp = *(const float4*)&proj[(size_t)(nb + jp) * 256 + c4];
            float4 pn = *(const float4*)&proj[(size_t)(nb + jn) * 256 + c4];
            float4 ps = *(const float4*)&proj[(size_t)(nb + j)  * 256 + c4];
            float v0 = ap * pp.x + an * pn.x + af * ps.x + hp0 + bv.x;
            float v1 = ap * pp.y + an * pn.y + af * ps.y + hp1 + bv.y;
            float v2 = ap * pp.z + an * pn.z + af * ps.z + hp2 + bv.z;
            float v3 = ap * pp.w + an * pn.w + af * ps.w + hp3 + bv.w;
            __nv_bfloat16 h0, l0, h1, l1, h2, l2, h3, l3;
            split_bf16(v0, h0, l0); split_bf16(v1, h1, l1);
            split_bf16(v2, h2, l2); split_bf16(v3, h3, l3);
            *(uint2*)&g_hhi[o] = make_uint2(pkbf2(h0, h1), pkbf2(h2, h3));
            *(uint2*)&g_hlo[o] = make_uint2(pkbf2(l0, l1), pkbf2(l2, l3));
        }
    }
}

// ---------------------------------------------------------------------------
extern "C" void kernel_launch(void* const* d_in, const int* in_sizes, int n_in,
                              void* d_out, int out_size)
{
    const float* x   = (const float*)d_in[0];
    const int*   t   = (const int*)  d_in[1];
    const float* tW  = (const float*)d_in[2];
    const float* tb  = (const float*)d_in[3];
    const float* W0  = (const float*)d_in[4];
    const float* as0 = (const float*)d_in[5];
    const float* at0 = (const float*)d_in[6];
    const float* b0  = (const float*)d_in[7];
    const float* W1  = (const float*)d_in[8];
    const float* as1 = (const float*)d_in[9];
    const float* at1 = (const float*)d_in[10];
    const float* b1  = (const float*)d_in[11];
    const float* W2  = (const float*)d_in[12];
    const float* as2 = (const float*)d_in[13];
    const float* at2 = (const float*)d_in[14];
    const float* b2_ = (const float*)d_in[15];
    const float* W3  = (const float*)d_in[16];
    const float* as3 = (const float*)d_in[17];
    const float* at3 = (const float*)d_in[18];
    const float* b3  = (const float*)d_in[19];
    const float* sk0 = (const float*)d_in[20];
    const float* sk1 = (const float*)d_in[21];
    const float* sk2 = (const float*)d_in[22];
    const float* h1W = (const float*)d_in[23];
    const float* h1b = (const float*)d_in[24];
    const float* h2W = (const float*)d_in[25];
    const float* h2b = (const float*)d_in[26];
    float* out = (float*)d_out;

    __nv_bfloat16 *hhi, *hlo, *w0hi, *w0lo, *w1hi, *w1lo, *w2hi, *w2lo, *w3hi, *w3lo, *h1hi, *h1lo;
    float *proj;
    cudaGetSymbolAddress((void**)&hhi,  g_hhi);
    cudaGetSymbolAddress((void**)&hlo,  g_hlo);
    cudaGetSymbolAddress((void**)&proj, g_proj);
    cudaGetSymbolAddress((void**)&w0hi, g_w0hi);  cudaGetSymbolAddress((void**)&w0lo, g_w0lo);
    cudaGetSymbolAddress((void**)&w1hi, g_w1hi);  cudaGetSymbolAddress((void**)&w1lo, g_w1lo);
    cudaGetSymbolAddress((void**)&w2hi, g_w2hi);  cudaGetSymbolAddress((void**)&w2lo, g_w2lo);
    cudaGetSymbolAddress((void**)&w3hi, g_w3hi);  cudaGetSymbolAddress((void**)&w3lo, g_w3lo);
    cudaGetSymbolAddress((void**)&h1hi, g_h1hi);  cudaGetSymbolAddress((void**)&h1lo, g_h1lo);

    const int GEMM_SMEM = 2 * STAGE_B;   // 81920
    cudaFuncSetAttribute(gemm_tc<0>, cudaFuncAttributeMaxDynamicSharedMemorySize, GEMM_SMEM);
    cudaFuncSetAttribute(gemm_tc<3>, cudaFuncAttributeMaxDynamicSharedMemorySize, GEMM_SMEM);

    const dim3 G512(4, NNODES / 128), G256(2, NNODES / 128);

    // prep everything up front (weights + out init), then temb/assemble
    prep_all<<<2368, 256>>>(W0, sk0, W1, sk1, W2, sk2, W3, h1W, h2b, out);
    temb_assemble<<<NPOLY, 256>>>(t, tW, tb, x);

    // layer 0: K=134 padded to 160
    gemm_tc<0><<<G512, 512, GEMM_SMEM>>>(hhi, hlo, w0hi, w0lo, 160, proj, 512, nullptr, nullptr);
    att_fuse4<<<NPOLY, 512>>>(proj, as0, at0, b0);

    // layer 1
    gemm_tc<0><<<G512, 512, GEMM_SMEM>>>(hhi, hlo, w1hi, w1lo, 256, proj, 512, nullptr, nullptr);
    att_fuse4<<<NPOLY, 512>>>(proj, as1, at1, b1);

    // layer 2
    gemm_tc<0><<<G512, 512, GEMM_SMEM>>>(hhi, hlo, w2hi, w2lo, 256, proj, 512, nullptr, nullptr);
    att_fuse4<<<NPOLY, 512>>>(proj, as2, at2, b2_);

    // layer 3 (NH=1, residual from hi+lo reconstruct, no act)
    gemm_tc<0><<<G256, 512, GEMM_SMEM>>>(hhi, hlo, w3hi, w3lo, 256, proj, 256, nullptr, nullptr);
    att_fuse1<<<NPOLY, 512>>>(proj, as3, at3, b3);

    // head: fused silu(h @ h1W + h1b) @ h2W + h2b -> out (atomics)
    gemm_tc<3><<<G256, 512, GEMM_SMEM>>>(hhi, hlo, h1hi, h1lo, 256, out, 2, h1b, h2W);
}

// round 16
// speedup vs baseline: 1.0566x; 1.0545x over previous
#include <cuda_runtime.h>
#include <cuda_bf16.h>
#include <cstdint>
#include <math.h>

// ---------------------------------------------------------------------------
// DenoiseGAT on GB300 — Round 16: R12's 256-thread GEMM (best) + R15's
// launch consolidation (prep_all, temb_assemble, per-layer weight buffers).
// ---------------------------------------------------------------------------

#define NPOLY  2048
#define VPOLY  64
#define NNODES (NPOLY * VPOLY)   // 131072

__device__ __align__(128) __nv_bfloat16 g_hhi[NNODES * 256];
__device__ __align__(128) __nv_bfloat16 g_hlo[NNODES * 256];
__device__ __align__(128) float          g_proj[NNODES * 512];
__device__ __align__(128) __nv_bfloat16 g_w0hi[512 * 160], g_w0lo[512 * 160];
__device__ __align__(128) __nv_bfloat16 g_w1hi[512 * 256], g_w1lo[512 * 256];
__device__ __align__(128) __nv_bfloat16 g_w2hi[512 * 256], g_w2lo[512 * 256];
__device__ __align__(128) __nv_bfloat16 g_w3hi[256 * 256], g_w3lo[256 * 256];
__device__ __align__(128) __nv_bfloat16 g_h1hi[256 * 256], g_h1lo[256 * 256];

__device__ __forceinline__ uint32_t smem_u32(const void* p) {
    uint32_t a;
    asm("{ .reg .u64 t; cvta.to.shared.u64 t, %1; cvt.u32.u64 %0, t; }" : "=r"(a) : "l"(p));
    return a;
}
__device__ __forceinline__ void cp16(uint32_t dst, const void* src) {
    asm volatile("cp.async.cg.shared.global [%0], [%1], 16;" :: "r"(dst), "l"(src) : "memory");
}
#define CP_COMMIT() asm volatile("cp.async.commit_group;" ::: "memory")
#define CP_WAIT0()  asm volatile("cp.async.wait_group 0;" ::: "memory")
#define CP_WAIT1()  asm volatile("cp.async.wait_group 1;" ::: "memory")

__device__ __forceinline__ void ldmx4(uint32_t& r0, uint32_t& r1, uint32_t& r2, uint32_t& r3, uint32_t addr) {
    asm volatile("ldmatrix.sync.aligned.m8n8.x4.shared.b16 {%0,%1,%2,%3}, [%4];"
                 : "=r"(r0), "=r"(r1), "=r"(r2), "=r"(r3) : "r"(addr));
}
__device__ __forceinline__ void mma_bf16(float* d, const uint32_t* a, const uint32_t* b) {
    asm volatile(
        "mma.sync.aligned.m16n8k16.row.col.f32.bf16.bf16.f32 "
        "{%0,%1,%2,%3}, {%4,%5,%6,%7}, {%8,%9}, {%0,%1,%2,%3};"
        : "+f"(d[0]), "+f"(d[1]), "+f"(d[2]), "+f"(d[3])
        : "r"(a[0]), "r"(a[1]), "r"(a[2]), "r"(a[3]), "r"(b[0]), "r"(b[1]));
}

__device__ __forceinline__ float lrelu02(float x) { return x >= 0.f ? x : 0.2f * x; }
__device__ __forceinline__ float eluf(float x)    { return x > 0.f ? x : (__expf(x) - 1.f); }
__device__ __forceinline__ float siluf(float x)   { return x / (1.f + __expf(-x)); }
__device__ __forceinline__ void split_bf16(float v, __nv_bfloat16& h, __nv_bfloat16& l) {
    h = __float2bfloat16(v);
    l = __float2bfloat16(v - __bfloat162float(h));
}
__device__ __forceinline__ uint32_t pkbf2(__nv_bfloat16 a, __nv_bfloat16 b) {
    __nv_bfloat162 t(a, b);
    return *reinterpret_cast<uint32_t*>(&t);
}
__device__ __forceinline__ float bf2lo(uint32_t p) {
    __nv_bfloat162 t = *reinterpret_cast<__nv_bfloat162*>(&p);
    return __bfloat162float(t.x);
}
__device__ __forceinline__ float bf2hi(uint32_t p) {
    __nv_bfloat162 t = *reinterpret_cast<__nv_bfloat162*>(&p);
    return __bfloat162float(t.y);
}

// ---------------------------------------------------------------------------
// HMMA GEMM (R12, best): 256 thr, warp grid 2m x 4n (64x32 warp tiles),
// CTA tile 128x128, K-tile 32, cp.async 2-stage, 80B rows, 2 CTAs/SM.
// MODE 0: plain store. MODE 3: fused head.
// ---------------------------------------------------------------------------
#define TILE_B   10240
#define STAGE_B  (4 * TILE_B)

template <int MODE>
__global__ __launch_bounds__(256, 2) void gemm_tc(
    const __nv_bfloat16* __restrict__ Ahi, const __nv_bfloat16* __restrict__ Alo,
    const __nv_bfloat16* __restrict__ Bhi, const __nv_bfloat16* __restrict__ Blo,
    int K, float* __restrict__ C, int ldc,
    const float* __restrict__ sv1, const float* __restrict__ sv2)
{
    extern __shared__ char smem[];
    const uint32_t sb = smem_u32(smem);

    const int tid  = threadIdx.x;
    const int lane = tid & 31;
    const int wid  = tid >> 5;
    const int wm   = wid & 1;
    const int wn   = wid >> 1;
    const int bm   = blockIdx.y * 128;
    const int bn   = blockIdx.x * 128;
    const int KT   = K >> 5;

    const int r0c = (tid) >> 2,        c0 = (tid & 3);
    const int r1c = (tid + 256) >> 2,  c1 = (tid & 3);

    float acc[4][4][4];
#pragma unroll
    for (int i = 0; i < 4; i++)
#pragma unroll
        for (int j = 0; j < 4; j++)
#pragma unroll
            for (int k = 0; k < 4; k++) acc[i][j][k] = 0.f;

#define ISSUE_STAGE(kt, s)                                                            \
    do {                                                                              \
        int kof = (kt) * 32;                                                          \
        uint32_t sba = sb + (s) * STAGE_B;                                            \
        cp16(sba + r0c * 80 + c0 * 16,              Ahi + (size_t)(bm + r0c) * K + kof + c0 * 8); \
        cp16(sba + r1c * 80 + c1 * 16,              Ahi + (size_t)(bm + r1c) * K + kof + c1 * 8); \
        cp16(sba + TILE_B + r0c * 80 + c0 * 16,     Alo + (size_t)(bm + r0c) * K + kof + c0 * 8); \
        cp16(sba + TILE_B + r1c * 80 + c1 * 16,     Alo + (size_t)(bm + r1c) * K + kof + c1 * 8); \
        cp16(sba + 2 * TILE_B + r0c * 80 + c0 * 16, Bhi + (size_t)(bn + r0c) * K + kof + c0 * 8); \
        cp16(sba + 2 * TILE_B + r1c * 80 + c1 * 16, Bhi + (size_t)(bn + r1c) * K + kof + c1 * 8); \
        cp16(sba + 3 * TILE_B + r0c * 80 + c0 * 16, Blo + (size_t)(bn + r0c) * K + kof + c0 * 8); \
        cp16(sba + 3 * TILE_B + r1c * 80 + c1 * 16, Blo + (size_t)(bn + r1c) * K + kof + c1 * 8); \
    } while (0)

    ISSUE_STAGE(0, 0);
    CP_COMMIT();

    const int aRow  = wm * 64 + (lane & 15);
    const int aHalf = lane >> 4;
    const int bRow  = wn * 32 + (lane & 7) + ((lane >> 4) << 3);
    const int bHalf = (lane >> 3) & 1;

    for (int kt = 0; kt < KT; kt++) {
        if (kt + 1 < KT) {
            ISSUE_STAGE(kt + 1, (kt + 1) & 1);
            CP_COMMIT();
            CP_WAIT1();
        } else {
            CP_WAIT0();
        }
        __syncthreads();

        const uint32_t sba = sb + (kt & 1) * STAGE_B;
#pragma unroll
        for (int ks = 0; ks < 2; ks++) {
            uint32_t Ah[4][4], Al[4][4], Bh[4][2], Bl[4][2];
#pragma unroll
            for (int mf = 0; mf < 4; mf++) {
                uint32_t ad = sba + (aRow + mf * 16) * 80 + (2 * ks + aHalf) * 16;
                ldmx4(Ah[mf][0], Ah[mf][1], Ah[mf][2], Ah[mf][3], ad);
                ldmx4(Al[mf][0], Al[mf][1], Al[mf][2], Al[mf][3], ad + TILE_B);
            }
#pragma unroll
            for (int nfp = 0; nfp < 2; nfp++) {
                uint32_t bd = sba + 2 * TILE_B + (bRow + nfp * 16) * 80 + (2 * ks + bHalf) * 16;
                uint32_t q0, q1, q2, q3;
                ldmx4(q0, q1, q2, q3, bd);
                Bh[nfp * 2][0] = q0; Bh[nfp * 2][1] = q1;
                Bh[nfp * 2 + 1][0] = q2; Bh[nfp * 2 + 1][1] = q3;
                ldmx4(q0, q1, q2, q3, bd + TILE_B);
                Bl[nfp * 2][0] = q0; Bl[nfp * 2][1] = q1;
                Bl[nfp * 2 + 1][0] = q2; Bl[nfp * 2 + 1][1] = q3;
            }
#pragma unroll
            for (int mf = 0; mf < 4; mf++)
#pragma unroll
                for (int nf = 0; nf < 4; nf++) {
                    mma_bf16(acc[mf][nf], Ah[mf], Bh[nf]);
                    mma_bf16(acc[mf][nf], Ah[mf], Bl[nf]);
                    mma_bf16(acc[mf][nf], Al[mf], Bh[nf]);
                }
        }
        __syncthreads();
    }

#pragma unroll
    for (int mf = 0; mf < 4; mf++) {
        int m0 = bm + wm * 64 + mf * 16 + (lane >> 2);
        float r0a = 0.f, r0b = 0.f, r1a = 0.f, r1b = 0.f;
#pragma unroll
        for (int nf = 0; nf < 4; nf++) {
            int n0 = bn + wn * 32 + nf * 8 + (lane & 3) * 2;
            float v0 = acc[mf][nf][0], v1 = acc[mf][nf][1];
            float v2 = acc[mf][nf][2], v3 = acc[mf][nf][3];
            if (MODE == 3) {
                float bb0 = sv1[n0], bb1 = sv1[n0 + 1];
                v0 = siluf(v0 + bb0); v1 = siluf(v1 + bb1);
                v2 = siluf(v2 + bb0); v3 = siluf(v3 + bb1);
                float w00 = sv2[n0 * 2],     w01 = sv2[n0 * 2 + 1];
                float w10 = sv2[n0 * 2 + 2], w11 = sv2[n0 * 2 + 3];
                r0a += v0 * w00 + v1 * w10;
                r0b += v0 * w01 + v1 * w11;
                r1a += v2 * w00 + v3 * w10;
                r1b += v2 * w01 + v3 * w11;
            } else {
                *(float2*)&C[(size_t)m0 * ldc + n0]       = make_float2(v0, v1);
                *(float2*)&C[(size_t)(m0 + 8) * ldc + n0] = make_float2(v2, v3);
            }
        }
        if (MODE == 3) {
            r0a += __shfl_xor_sync(0xffffffffu, r0a, 1);
            r0a += __shfl_xor_sync(0xffffffffu, r0a, 2);
            r0b += __shfl_xor_sync(0xffffffffu, r0b, 1);
            r0b += __shfl_xor_sync(0xffffffffu, r0b, 2);
            r1a += __shfl_xor_sync(0xffffffffu, r1a, 1);
            r1a += __shfl_xor_sync(0xffffffffu, r1a, 2);
            r1b += __shfl_xor_sync(0xffffffffu, r1b, 1);
            r1b += __shfl_xor_sync(0xffffffffu, r1b, 2);
            if ((lane & 3) == 0) {
                atomicAdd(&C[(size_t)m0 * 2],           r0a);
                atomicAdd(&C[(size_t)m0 * 2 + 1],       r0b);
                atomicAdd(&C[(size_t)(m0 + 8) * 2],     r1a);
                atomicAdd(&C[(size_t)(m0 + 8) * 2 + 1], r1b);
            }
        }
    }
}

// ---------------------------------------------------------------------------
// prep_all: all weight splits + out init in one launch (R15).
// ---------------------------------------------------------------------------
__global__ void prep_all(
    const float* __restrict__ W0, const float* __restrict__ sk0,
    const float* __restrict__ W1, const float* __restrict__ sk1,
    const float* __restrict__ W2, const float* __restrict__ sk2,
    const float* __restrict__ W3, const float* __restrict__ h1W,
    const float* __restrict__ h2b, float* __restrict__ out)
{
    int idx = blockIdx.x * 256 + threadIdx.x;
    if (idx < 81920) {                       // L0: [W0|sk0]^T, Kpad=160, K=134
        int n = idx / 160, k = idx % 160;
        float v = 0.f;
        if (k < 134) v = (n < 256) ? W0[k * 256 + n] : sk0[k * 256 + (n - 256)];
        __nv_bfloat16 h, l; split_bf16(v, h, l);
        g_w0hi[idx] = h; g_w0lo[idx] = l;
    } else if (idx < 212992) {               // L1
        int i = idx - 81920, n = i >> 8, k = i & 255;
        float v = (n < 256) ? W1[k * 256 + n] : sk1[k * 256 + (n - 256)];
        __nv_bfloat16 h, l; split_bf16(v, h, l);
        g_w1hi[i] = h; g_w1lo[i] = l;
    } else if (idx < 344064) {               // L2
        int i = idx - 212992, n = i >> 8, k = i & 255;
        float v = (n < 256) ? W2[k * 256 + n] : sk2[k * 256 + (n - 256)];
        __nv_bfloat16 h, l; split_bf16(v, h, l);
        g_w2hi[i] = h; g_w2lo[i] = l;
    } else if (idx < 409600) {               // W3^T
        int i = idx - 344064, n = i >> 8, k = i & 255;
        float v = W3[k * 256 + n];
        __nv_bfloat16 h, l; split_bf16(v, h, l);
        g_w3hi[i] = h; g_w3lo[i] = l;
    } else if (idx < 475136) {               // h1W^T
        int i = idx - 409600, n = i >> 8, k = i & 255;
        float v = h1W[k * 256 + n];
        __nv_bfloat16 h, l; split_bf16(v, h, l);
        g_h1hi[i] = h; g_h1lo[i] = l;
    } else if (idx < 606208) {               // init out = h2b
        int i = idx - 475136;
        *(float2*)&out[(size_t)i * 2] = make_float2(h2b[0], h2b[1]);
    }
}

// ---------------------------------------------------------------------------
// temb + assemble fused (R15): one block per polygon, 256 threads.
// ---------------------------------------------------------------------------
__global__ __launch_bounds__(256) void temb_assemble(
    const int* __restrict__ t, const float* __restrict__ tW,
    const float* __restrict__ tb, const float* __restrict__ x)
{
    __shared__ float pe[128], te[128];
    const int b = blockIdx.x, tid = threadIdx.x;
    float tv = (float)t[b];
    if (tid < 64) {
        float fr = expf(-logf(10000.0f) * (float)tid * (1.0f / 63.0f));
        float a = tv * fr;
        pe[tid]      = sinf(a);
        pe[tid + 64] = cosf(a);
    }
    __syncthreads();
    if (tid < 128) {
        float acc = tb[tid];
#pragma unroll 8
        for (int k = 0; k < 128; k++) acc += pe[k] * tW[k * 128 + tid];
        te[tid] = siluf(acc);
    }
    __syncthreads();
    for (int i = tid; i < 64 * 160; i += 256) {
        int v = i / 160, c = i % 160;
        int n = b * 64 + v;
        float val = 0.f;
        if (c < 2) {
            val = x[b * 128 + v * 2 + c];
        } else if (c < 6) {
            float ph  = (float)v * (6.283185307179586f / 64.f);
            float arg = (c < 4) ? ph : 2.f * ph;
            val = ((c & 1) == 0) ? sinf(arg) : cosf(arg);
        } else if (c < 134) {
            val = te[c - 6];
        }
        __nv_bfloat16 h, l;
        split_bf16(val, h, l);
        g_hhi[(size_t)n * 160 + c] = h;
        g_hlo[(size_t)n * 160 + c] = l;
    }
}

// ---------------------------------------------------------------------------
// Fused thin attention, 4 heads (R12).
// ---------------------------------------------------------------------------
__global__ __launch_bounds__(512) void att_fuse4(
    const float* __restrict__ proj,     // N x 512
    const float* __restrict__ asrc, const float* __restrict__ atgt,
    const float* __restrict__ bias)
{
    __shared__ float sS[256], sT[256], aP[256], aN[256], aSf[256], sa[256], sg[256];
    const int tid = threadIdx.x, lane = tid & 31, wid = tid >> 5;
    const int nb  = blockIdx.x * 64;

    if (tid < 256) { sa[tid] = asrc[tid]; sg[tid] = atgt[tid]; }
    __syncthreads();

    {
        const int h = lane >> 3;
        const int cbase = lane * 8;
#pragma unroll
        for (int r = 0; r < 4; r++) {
            int j = wid * 4 + r;
            const float4* rp = (const float4*)(proj + (size_t)(nb + j) * 512 + cbase);
            float4 x0 = rp[0], x1 = rp[1];
            const float* wa = sa + cbase;
            const float* wg = sg + cbase;
            float ss = x0.x * wa[0] + x0.y * wa[1] + x0.z * wa[2] + x0.w * wa[3]
                     + x1.x * wa[4] + x1.y * wa[5] + x1.z * wa[6] + x1.w * wa[7];
            float st = x0.x * wg[0] + x0.y * wg[1] + x0.z * wg[2] + x0.w * wg[3]
                     + x1.x * wg[4] + x1.y * wg[5] + x1.z * wg[6] + x1.w * wg[7];
            ss += __shfl_xor_sync(0xffffffffu, ss, 1);
            st += __shfl_xor_sync(0xffffffffu, st, 1);
            ss += __shfl_xor_sync(0xffffffffu, ss, 2);
            st += __shfl_xor_sync(0xffffffffu, st, 2);
            ss += __shfl_xor_sync(0xffffffffu, ss, 4);
            st += __shfl_xor_sync(0xffffffffu, st, 4);
            if ((lane & 7) == 0) { sS[j * 4 + h] = ss; sT[j * 4 + h] = st; }
        }
    }
    __syncthreads();

    if (tid < 256) {
        int j = tid >> 2, hh = tid & 3;
        int jp = (j + 63) & 63, jn = (j + 1) & 63;
        float tg = sT[j * 4 + hh];
        float ep = lrelu02(sS[jp * 4 + hh] + tg);
        float en = lrelu02(sS[jn * 4 + hh] + tg);
        float es = lrelu02(sS[j * 4 + hh]  + tg);
        float m  = fmaxf(ep, fmaxf(en, es));
        ep = __expf(ep - m); en = __expf(en - m); es = __expf(es - m);
        float inv = 1.f / (ep + en + es + 1e-16f);
        aP[j * 4 + hh]  = ep * inv;
        aN[j * 4 + hh]  = en * inv;
        aSf[j * 4 + hh] = es * inv;
    }
    __syncthreads();

    {
        const int c4 = (tid & 63) << 2;
        const int j0 = (tid >> 6) << 3;
        const int h  = c4 >> 6;
        const float4 bv = *(const float4*)&bias[c4];
#pragma unroll
        for (int jj = 0; jj < 8; jj++) {
            int j = j0 + jj, jp = (j + 63) & 63, jn = (j + 1) & 63;
            float ap = aP[j * 4 + h], an = aN[j * 4 + h], af = aSf[j * 4 + h];
            float4 pp = *(const float4*)&proj[(size_t)(nb + jp) * 512 + c4];
            float4 pn = *(const float4*)&proj[(size_t)(nb + jn) * 512 + c4];
            float4 ps = *(const float4*)&proj[(size_t)(nb + j)  * 512 + c4];
            float4 sk = *(const float4*)&proj[(size_t)(nb + j)  * 512 + 256 + c4];
            float v0 = eluf(ap * pp.x + an * pn.x + af * ps.x + sk.x + bv.x);
            float v1 = eluf(ap * pp.y + an * pn.y + af * ps.y + sk.y + bv.y);
            float v2 = eluf(ap * pp.z + an * pn.z + af * ps.z + sk.z + bv.z);
            float v3 = eluf(ap * pp.w + an * pn.w + af * ps.w + sk.w + bv.w);
            __nv_bfloat16 h0, l0, h1, l1, h2, l2, h3, l3;
            split_bf16(v0, h0, l0); split_bf16(v1, h1, l1);
            split_bf16(v2, h2, l2); split_bf16(v3, h3, l3);
            size_t o = (size_t)(nb + j) * 256 + c4;
            *(uint2*)&g_hhi[o] = make_uint2(pkbf2(h0, h1), pkbf2(h2, h3));
            *(uint2*)&g_hlo[o] = make_uint2(pkbf2(l0, l1), pkbf2(l2, l3));
        }
    }
}

// ---------------------------------------------------------------------------
// Fused thin attention, 1 head (R12): residual from hi+lo, no act.
// ---------------------------------------------------------------------------
__global__ __launch_bounds__(512) void att_fuse1(
    const float* __restrict__ proj,     // N x 256
    const float* __restrict__ asrc, const float* __restrict__ atgt,
    const float* __restrict__ bias)
{
    __shared__ float sS[64], sT[64], aP[64], aN[64], aSf[64], sa[256], sg[256];
    const int tid = threadIdx.x, lane = tid & 31, wid = tid >> 5;
    const int nb  = blockIdx.x * 64;

    if (tid < 256) { sa[tid] = asrc[tid]; sg[tid] = atgt[tid]; }
    __syncthreads();

    {
        const int cbase = lane * 8;
#pragma unroll
        for (int r = 0; r < 4; r++) {
            int j = wid * 4 + r;
            const float4* rp = (const float4*)(proj + (size_t)(nb + j) * 256 + cbase);
            float4 x0 = rp[0], x1 = rp[1];
            const float* wa = sa + cbase;
            const float* wg = sg + cbase;
            float ss = x0.x * wa[0] + x0.y * wa[1] + x0.z * wa[2] + x0.w * wa[3]
                     + x1.x * wa[4] + x1.y * wa[5] + x1.z * wa[6] + x1.w * wa[7];
            float st = x0.x * wg[0] + x0.y * wg[1] + x0.z * wg[2] + x0.w * wg[3]
                     + x1.x * wg[4] + x1.y * wg[5] + x1.z * wg[6] + x1.w * wg[7];
#pragma unroll
            for (int off = 16; off; off >>= 1) {
                ss += __shfl_xor_sync(0xffffffffu, ss, off);
                st += __shfl_xor_sync(0xffffffffu, st, off);
            }
            if (lane == 0) { sS[j] = ss; sT[j] = st; }
        }
    }
    __syncthreads();

    if (tid < 64) {
        int j = tid, jp = (j + 63) & 63, jn = (j + 1) & 63;
        float tg = sT[j];
        float ep = lrelu02(sS[jp] + tg);
        float en = lrelu02(sS[jn] + tg);
        float es = lrelu02(sS[j]  + tg);
        float m  = fmaxf(ep, fmaxf(en, es));
        ep = __expf(ep - m); en = __expf(en - m); es = __expf(es - m);
        float inv = 1.f / (ep + en + es + 1e-16f);
        aP[j] = ep * inv; aN[j] = en * inv; aSf[j] = es * inv;
    }
    __syncthreads();

    {
        const int c4 = (tid & 63) << 2;
        const int j0 = (tid >> 6) << 3;
        const float4 bv = *(const float4*)&bias[c4];
#pragma unroll
        for (int jj = 0; jj < 8; jj++) {
            int j = j0 + jj, jp = (j + 63) & 63, jn = (j + 1) & 63;
            float ap = aP[j], an = aN[j], af = aSf[j];
            size_t o = (size_t)(nb + j) * 256 + c4;
            uint2 uh = *(uint2*)&g_hhi[o];
            uint2 ul = *(uint2*)&g_hlo[o];
            float hp0 = bf2lo(uh.x) + bf2lo(ul.x);
            float hp1 = bf2hi(uh.x) + bf2hi(ul.x);
            float hp2 = bf2lo(uh.y) + bf2lo(ul.y);
            float hp3 = bf2hi(uh.y) + bf2hi(ul.y);
            float4 pp = *(const float4*)&proj[(size_t)(nb + jp) * 256 + c4];
            float4 pn = *(const float4*)&proj[(size_t)(nb + jn) * 256 + c4];
            float4 ps = *(const float4*)&proj[(size_t)(nb + j)  * 256 + c4];
            float v0 = ap * pp.x + an * pn.x + af * ps.x + hp0 + bv.x;
            float v1 = ap * pp.y + an * pn.y + af * ps.y + hp1 + bv.y;
            float v2 = ap * pp.z + an * pn.z + af * ps.z + hp2 + bv.z;
            float v3 = ap * pp.w + an * pn.w + af * ps.w + hp3 + bv.w;
            __nv_bfloat16 h0, l0, h1, l1, h2, l2, h3, l3;
            split_bf16(v0, h0, l0); split_bf16(v1, h1, l1);
            split_bf16(v2, h2, l2); split_bf16(v3, h3, l3);
            *(uint2*)&g_hhi[o] = make_uint2(pkbf2(h0, h1), pkbf2(h2, h3));
            *(uint2*)&g_hlo[o] = make_uint2(pkbf2(l0, l1), pkbf2(l2, l3));
        }
    }
}

// ---------------------------------------------------------------------------
extern "C" void kernel_launch(void* const* d_in, const int* in_sizes, int n_in,
                              void* d_out, int out_size)
{
    const float* x   = (const float*)d_in[0];
    const int*   t   = (const int*)  d_in[1];
    const float* tW  = (const float*)d_in[2];
    const float* tb  = (const float*)d_in[3];
    const float* W0  = (const float*)d_in[4];
    const float* as0 = (const float*)d_in[5];
    const float* at0 = (const float*)d_in[6];
    const float* b0  = (const float*)d_in[7];
    const float* W1  = (const float*)d_in[8];
    const float* as1 = (const float*)d_in[9];
    const float* at1 = (const float*)d_in[10];
    const float* b1  = (const float*)d_in[11];
    const float* W2  = (const float*)d_in[12];
    const float* as2 = (const float*)d_in[13];
    const float* at2 = (const float*)d_in[14];
    const float* b2_ = (const float*)d_in[15];
    const float* W3  = (const float*)d_in[16];
    const float* as3 = (const float*)d_in[17];
    const float* at3 = (const float*)d_in[18];
    const float* b3  = (const float*)d_in[19];
    const float* sk0 = (const float*)d_in[20];
    const float* sk1 = (const float*)d_in[21];
    const float* sk2 = (const float*)d_in[22];
    const float* h1W = (const float*)d_in[23];
    const float* h1b = (const float*)d_in[24];
    const float* h2W = (const float*)d_in[25];
    const float* h2b = (const float*)d_in[26];
    float* out = (float*)d_out;

    __nv_bfloat16 *hhi, *hlo, *w0hi, *w0lo, *w1hi, *w1lo, *w2hi, *w2lo, *w3hi, *w3lo, *h1hi, *h1lo;
    float *proj;
    cudaGetSymbolAddress((void**)&hhi,  g_hhi);
    cudaGetSymbolAddress((void**)&hlo,  g_hlo);
    cudaGetSymbolAddress((void**)&proj, g_proj);
    cudaGetSymbolAddress((void**)&w0hi, g_w0hi);  cudaGetSymbolAddress((void**)&w0lo, g_w0lo);
    cudaGetSymbolAddress((void**)&w1hi, g_w1hi);  cudaGetSymbolAddress((void**)&w1lo, g_w1lo);
    cudaGetSymbolAddress((void**)&w2hi, g_w2hi);  cudaGetSymbolAddress((void**)&w2lo, g_w2lo);
    cudaGetSymbolAddress((void**)&w3hi, g_w3hi);  cudaGetSymbolAddress((void**)&w3lo, g_w3lo);
    cudaGetSymbolAddress((void**)&h1hi, g_h1hi);  cudaGetSymbolAddress((void**)&h1lo, g_h1lo);

    const int GEMM_SMEM = 2 * STAGE_B;   // 81920
    cudaFuncSetAttribute(gemm_tc<0>, cudaFuncAttributeMaxDynamicSharedMemorySize, GEMM_SMEM);
    cudaFuncSetAttribute(gemm_tc<3>, cudaFuncAttributeMaxDynamicSharedMemorySize, GEMM_SMEM);

    const dim3 G512(4, NNODES / 128), G256(2, NNODES / 128);

    // prep everything up front (weights + out init), then temb/assemble
    prep_all<<<2368, 256>>>(W0, sk0, W1, sk1, W2, sk2, W3, h1W, h2b, out);
    temb_assemble<<<NPOLY, 256>>>(t, tW, tb, x);

    // layer 0: K=134 padded to 160
    gemm_tc<0><<<G512, 256, GEMM_SMEM>>>(hhi, hlo, w0hi, w0lo, 160, proj, 512, nullptr, nullptr);
    att_fuse4<<<NPOLY, 512>>>(proj, as0, at0, b0);

    // layer 1
    gemm_tc<0><<<G512, 256, GEMM_SMEM>>>(hhi, hlo, w1hi, w1lo, 256, proj, 512, nullptr, nullptr);
    att_fuse4<<<NPOLY, 512>>>(proj, as1, at1, b1);

    // layer 2
    gemm_tc<0><<<G512, 256, GEMM_SMEM>>>(hhi, hlo, w2hi, w2lo, 256, proj, 512, nullptr, nullptr);
    att_fuse4<<<NPOLY, 512>>>(proj, as2, at2, b2_);

    // layer 3 (NH=1, residual from hi+lo reconstruct, no act)
    gemm_tc<0><<<G256, 256, GEMM_SMEM>>>(hhi, hlo, w3hi, w3lo, 256, proj, 256, nullptr, nullptr);
    att_fuse1<<<NPOLY, 512>>>(proj, as3, at3, b3);

    // head: fused silu(h @ h1W + h1b) @ h2W + h2b -> out (atomics)
    gemm_tc<3><<<G256, 256, GEMM_SMEM>>>(hhi, hlo, h1hi, h1lo, 256, out, 2, h1b, h2W);
}